// round 7
// baseline (speedup 1.0000x reference)
#include <cuda_runtime.h>
#include <cuda_bf16.h>
#include <math.h>

// ---------------------------------------------------------------------------
// Problem constants
// ---------------------------------------------------------------------------
#define BB   2
#define SS   1024
#define NBAR 64
#define DD   512
#define HH   8
#define DHH  64
#define FF   2048
#define LL   12
#define VV   1024

#define RR   (BB*SS)      // 2048
#define SRR  (BB*NBAR)    // 128
#define KTOT (NBAR+SS)    // 1088
#define QKVLD 1536        // packed QKV row stride

// ---------------------------------------------------------------------------
// Device scratch
// ---------------------------------------------------------------------------
__device__ float g_x    [RR*DD];
__device__ float g_sum  [SRR*DD];
__device__ float g_lnr  [RR*DD];
__device__ float g_lns  [SRR*DD];
__device__ float g_qkvr [RR*QKVLD];
__device__ float g_qkvs [SRR*QKVLD];
__device__ float g_Or   [RR*DD];
__device__ float g_Os   [SRR*DD];
__device__ float g_h1r  [RR*FF];
__device__ float g_h3r  [RR*FF];
__device__ float g_h1s  [SRR*FF];
__device__ float g_h3s  [SRR*FF];
__device__ float g_wqkv [LL*DD*3*DD];

// ---------------------------------------------------------------------------
// bf16 split helpers
// ---------------------------------------------------------------------------
__device__ __forceinline__ uint2 split_pack(float x0, float x1) {
    __nv_bfloat16 h0 = __float2bfloat16(x0);
    __nv_bfloat16 h1 = __float2bfloat16(x1);
    float r0 = x0 - __bfloat162float(h0);
    float r1 = x1 - __bfloat162float(h1);
    __nv_bfloat16 l0 = __float2bfloat16(r0);
    __nv_bfloat16 l1 = __float2bfloat16(r1);
    uint2 t;
    t.x = ((unsigned)__bfloat16_as_ushort(h1) << 16) | __bfloat16_as_ushort(h0);
    t.y = ((unsigned)__bfloat16_as_ushort(l1) << 16) | __bfloat16_as_ushort(l0);
    return t;
}

__device__ __forceinline__ void mma_bf16(float c[4],
                                         unsigned a0, unsigned a1, unsigned a2, unsigned a3,
                                         unsigned b0, unsigned b1) {
    asm volatile(
        "mma.sync.aligned.m16n8k16.row.col.f32.bf16.bf16.f32 "
        "{%0,%1,%2,%3}, {%4,%5,%6,%7}, {%8,%9}, {%0,%1,%2,%3};"
        : "+f"(c[0]), "+f"(c[1]), "+f"(c[2]), "+f"(c[3])
        : "r"(a0), "r"(a1), "r"(a2), "r"(a3), "r"(b0), "r"(b1));
}

__device__ __forceinline__ float silu(float x) {
    return x / (1.0f + __expf(-x));
}

// ---------------------------------------------------------------------------
// bf16x3 tensor-core GEMM.  C[M,N] = A[M,K] @ B  (B: KxN, or NxK if TRANSB)
// Block 128x128, BK=16, 256 threads, 8 warps at 64x32 each.
// hi/lo interleaved uint2 smem; register-prefetch pipeline.
// SWI: A := silu(A) * A3 applied during the A load (for FFN w2).
// Requires M%128==0, N%128==0, K%16==0.
// ---------------------------------------------------------------------------
#define AMP 132
#define BNP 132

template<int TRANSB, int ACC, int SWI>
__global__ void __launch_bounds__(256)
mma_gemm(const float* __restrict__ A, const float* __restrict__ A3,
         const float* __restrict__ B, float* __restrict__ C,
         int M, int N, int K) {
    __shared__ uint2 As[8 * AMP];
    __shared__ uint2 Bs[8 * BNP];

    int tid = threadIdx.x;
    int m0 = blockIdx.y * 128, n0 = blockIdx.x * 128;
    int wid = tid >> 5, lane = tid & 31;
    int wm = (wid >> 2) * 64, wn = (wid & 3) * 32;
    int g = lane >> 2, tig = lane & 3;

    // A (and TRANSB-B) loader mapping: row = tid>>1, k-segment 0 or 8
    int arow = tid >> 1, aseg = (tid & 1) * 8;
    // no-trans B loader mapping: n = tid&127, pair group 0 or 4
    int bn = tid & 127, pgrp = (tid >> 7) * 4;

    const float* Aptr  = A  + (size_t)(m0 + arow) * K + aseg;
    const float* A3ptr = SWI ? (A3 + (size_t)(m0 + arow) * K + aseg) : A;
    const float* Btr   = TRANSB ? (B + (size_t)(n0 + arow) * K + aseg) : B;
    const float* Bnt   = TRANSB ? B : (B + n0 + bn);

    float4 la0, la1, la30, la31, lbt0, lbt1;
    float lb[8];

    // prologue: chunk 0
    la0 = *(const float4*)(Aptr);
    la1 = *(const float4*)(Aptr + 4);
    if (SWI) { la30 = *(const float4*)(A3ptr); la31 = *(const float4*)(A3ptr + 4); }
    if (TRANSB) {
        lbt0 = *(const float4*)(Btr);
        lbt1 = *(const float4*)(Btr + 4);
    } else {
        #pragma unroll
        for (int pp = 0; pp < 4; pp++) {
            lb[2*pp+0] = Bnt[(size_t)(2*(pgrp+pp)  ) * N];
            lb[2*pp+1] = Bnt[(size_t)(2*(pgrp+pp)+1) * N];
        }
    }

    float c[4][4][4] = {};
    int p0 = aseg >> 1;

    for (int k0 = 0; k0 < K; k0 += 16) {
        // ---- stage current chunk into smem ----
        float4 va0 = la0, va1 = la1;
        if (SWI) {
            va0.x = silu(va0.x) * la30.x; va0.y = silu(va0.y) * la30.y;
            va0.z = silu(va0.z) * la30.z; va0.w = silu(va0.w) * la30.w;
            va1.x = silu(va1.x) * la31.x; va1.y = silu(va1.y) * la31.y;
            va1.z = silu(va1.z) * la31.z; va1.w = silu(va1.w) * la31.w;
        }
        As[(p0+0)*AMP + arow] = split_pack(va0.x, va0.y);
        As[(p0+1)*AMP + arow] = split_pack(va0.z, va0.w);
        As[(p0+2)*AMP + arow] = split_pack(va1.x, va1.y);
        As[(p0+3)*AMP + arow] = split_pack(va1.z, va1.w);
        if (TRANSB) {
            Bs[(p0+0)*BNP + arow] = split_pack(lbt0.x, lbt0.y);
            Bs[(p0+1)*BNP + arow] = split_pack(lbt0.z, lbt0.w);
            Bs[(p0+2)*BNP + arow] = split_pack(lbt1.x, lbt1.y);
            Bs[(p0+3)*BNP + arow] = split_pack(lbt1.z, lbt1.w);
        } else {
            #pragma unroll
            for (int pp = 0; pp < 4; pp++)
                Bs[(pgrp+pp)*BNP + bn] = split_pack(lb[2*pp], lb[2*pp+1]);
        }
        __syncthreads();

        // ---- prefetch next chunk into registers ----
        if (k0 + 16 < K) {
            la0 = *(const float4*)(Aptr + k0 + 16);
            la1 = *(const float4*)(Aptr + k0 + 20);
            if (SWI) {
                la30 = *(const float4*)(A3ptr + k0 + 16);
                la31 = *(const float4*)(A3ptr + k0 + 20);
            }
            if (TRANSB) {
                lbt0 = *(const float4*)(Btr + k0 + 16);
                lbt1 = *(const float4*)(Btr + k0 + 20);
            } else {
                #pragma unroll
                for (int pp = 0; pp < 4; pp++) {
                    lb[2*pp+0] = Bnt[(size_t)(k0 + 16 + 2*(pgrp+pp)  ) * N];
                    lb[2*pp+1] = Bnt[(size_t)(k0 + 16 + 2*(pgrp+pp)+1) * N];
                }
            }
        }

        // ---- compute ----
        uint2 af[4][4];
        #pragma unroll
        for (int mt = 0; mt < 4; mt++) {
            int mr = wm + mt * 16 + g;
            af[mt][0] = As[(tig  )*AMP + mr];
            af[mt][1] = As[(tig  )*AMP + mr + 8];
            af[mt][2] = As[(tig+4)*AMP + mr];
            af[mt][3] = As[(tig+4)*AMP + mr + 8];
        }
        uint2 bf[4][2];
        #pragma unroll
        for (int nt = 0; nt < 4; nt++) {
            int nc = wn + nt * 8 + g;
            bf[nt][0] = Bs[(tig  )*BNP + nc];
            bf[nt][1] = Bs[(tig+4)*BNP + nc];
        }
        #pragma unroll
        for (int mt = 0; mt < 4; mt++)
            #pragma unroll
            for (int nt = 0; nt < 4; nt++) {
                mma_bf16(c[mt][nt], af[mt][0].x, af[mt][1].x, af[mt][2].x, af[mt][3].x,
                         bf[nt][0].x, bf[nt][1].x);
                mma_bf16(c[mt][nt], af[mt][0].x, af[mt][1].x, af[mt][2].x, af[mt][3].x,
                         bf[nt][0].y, bf[nt][1].y);
                mma_bf16(c[mt][nt], af[mt][0].y, af[mt][1].y, af[mt][2].y, af[mt][3].y,
                         bf[nt][0].x, bf[nt][1].x);
            }
        __syncthreads();
    }

    #pragma unroll
    for (int mt = 0; mt < 4; mt++) {
        #pragma unroll
        for (int r = 0; r < 2; r++) {
            int row = m0 + wm + mt * 16 + g + r * 8;
            #pragma unroll
            for (int nt = 0; nt < 4; nt++) {
                int col = n0 + wn + nt * 8 + tig * 2;
                float2* cp = (float2*)(C + (size_t)row * N + col);
                float v0 = c[mt][nt][r*2+0], v1 = c[mt][nt][r*2+1];
                if (ACC) {
                    float2 o = *cp; o.x += v0; o.y += v1; *cp = o;
                } else {
                    float2 o; o.x = v0; o.y = v1; *cp = o;
                }
            }
        }
    }
}

// ---------------------------------------------------------------------------
// QKV weight packing: wqkv[l][k][0:512]=Wq, [512:1024]=Wk, [1024:1536]=Wv
// ---------------------------------------------------------------------------
__global__ void pack_qkv_kernel(const float* __restrict__ Wq,
                                const float* __restrict__ Wk,
                                const float* __restrict__ Wv,
                                float* __restrict__ out) {
    int total = LL * DD * 3 * DD;
    for (int idx = blockIdx.x * blockDim.x + threadIdx.x; idx < total;
         idx += gridDim.x * blockDim.x) {
        int j = idx % (3*DD);
        int rest = idx / (3*DD);
        // rest = l*DD + k
        float v;
        if (j < DD)            v = Wq[(size_t)rest * DD + j];
        else if (j < 2*DD)     v = Wk[(size_t)rest * DD + (j - DD)];
        else                   v = Wv[(size_t)rest * DD + (j - 2*DD)];
        out[idx] = v;
    }
}

// ---------------------------------------------------------------------------
// Embedding init
// ---------------------------------------------------------------------------
__global__ void embed_kernel(const int* __restrict__ tok,
                             const int* __restrict__ inst,
                             const float* __restrict__ tok_emb,
                             const float* __restrict__ inst_emb,
                             float* __restrict__ x) {
    int row = blockIdx.x;
    int t = tok[row];
    int ii = inst[row]; ii = ii < 0 ? 0 : (ii > 129 ? 129 : ii);
    const float4* te = (const float4*)(tok_emb  + (size_t)t  * DD);
    const float4* ie = (const float4*)(inst_emb + (size_t)ii * DD);
    float4* xo = (float4*)(x + (size_t)row * DD);
    for (int d = threadIdx.x; d < DD/4; d += blockDim.x) {
        float4 a = te[d], b = ie[d];
        xo[d] = make_float4(a.x+b.x, a.y+b.y, a.z+b.z, a.w+b.w);
    }
}

__global__ void sum_init_kernel(const float* __restrict__ bar_emb,
                                float* __restrict__ sum_x) {
    int row = blockIdx.x;
    int bar = row % NBAR;
    const float4* be = (const float4*)(bar_emb + (size_t)bar * DD);
    float4* so = (float4*)(sum_x + (size_t)row * DD);
    for (int d = threadIdx.x; d < DD/4; d += blockDim.x) so[d] = be[d];
}

// ---------------------------------------------------------------------------
// LayerNorm
// ---------------------------------------------------------------------------
__global__ void __launch_bounds__(256)
ln_kernel(const float* __restrict__ in,
          const float* __restrict__ g,
          const float* __restrict__ b,
          float* __restrict__ out) {
    int row = blockIdx.x;
    int tid = threadIdx.x;
    const float* xr = in + (size_t)row * DD;
    float v0 = xr[tid], v1 = xr[tid + 256];
    __shared__ float sh[256];
    sh[tid] = v0 + v1; __syncthreads();
    for (int o = 128; o > 0; o >>= 1) { if (tid < o) sh[tid] += sh[tid+o]; __syncthreads(); }
    float mean = sh[0] * (1.0f/DD);
    __syncthreads();
    float d0 = v0 - mean, d1 = v1 - mean;
    sh[tid] = d0*d0 + d1*d1; __syncthreads();
    for (int o = 128; o > 0; o >>= 1) { if (tid < o) sh[tid] += sh[tid+o]; __syncthreads(); }
    float r = rsqrtf(sh[0] * (1.0f/DD) + 1e-5f);
    float* orow = out + (size_t)row * DD;
    orow[tid]       = d0 * r * g[tid]       + b[tid];
    orow[tid + 256] = d1 * r * g[tid + 256] + b[tid + 256];
}

// ---------------------------------------------------------------------------
// RoPE over packed QKV buffer: rotates head-slices 0..15 (Q heads + K heads),
// leaves V (cols 1024..1535) untouched. Row stride QKVLD.
// ---------------------------------------------------------------------------
__global__ void rope_kernel(float* __restrict__ buf, int rows, int posMod) {
    const float LOGF = 9.210340371976184f / 32.0f;
    int total = rows * 16 * 32;
    for (int idx = blockIdx.x * blockDim.x + threadIdx.x; idx < total;
         idx += gridDim.x * blockDim.x) {
        int row  = idx >> 9;
        int rem  = idx & 511;
        int head = rem >> 5;
        int d    = rem & 31;
        int pos  = row % posMod;
        float inv = __expf(-(float)d * LOGF);
        float f = (float)pos * inv;
        float c, s; __sincosf(f, &s, &c);
        float* p = buf + (size_t)row * QKVLD + head * 64;
        float x1 = p[d], x2 = p[d + 32];
        p[d]      = x1 * c - x2 * s;
        p[d + 32] = x1 * s + x2 * c;
    }
}

// ---------------------------------------------------------------------------
// Range-based sparse attention over packed QKV buffers.
// ---------------------------------------------------------------------------
template<int SUMQ>
__global__ void __launch_bounds__(64)
attn_kernel(const float* __restrict__ qkvS,
            const float* __restrict__ qkvR,
            const int*  __restrict__ chord,
            float* __restrict__ O) {
    const int QN = SUMQ ? NBAR : SS;
    int qrow = blockIdx.x;
    int h    = blockIdx.y;
    int tid  = threadIdx.x;
    int b    = qrow / QN;
    int qi   = qrow % QN;
    const int* ch = chord + b * SS;
    const float* qkvQ = SUMQ ? qkvS : qkvR;

    __shared__ float shq[DHH];
    __shared__ float sc[KTOT];
    __shared__ float red[64];

    if (tid < DHH) shq[tid] = qkvQ[(size_t)qrow * QKVLD + h * DHH + tid];

    int target = SUMQ ? qi : ch[qi];
    int lo = 0, hi = SS;
    while (lo < hi) { int mid = (lo + hi) >> 1; if (ch[mid] < target) lo = mid + 1; else hi = mid; }
    int tstart = lo;
    int n1, n2;
    if (SUMQ) {
        int lo2 = tstart, hi2 = SS;
        while (lo2 < hi2) { int mid = (lo2 + hi2) >> 1; if (ch[mid] < target + 1) lo2 = mid + 1; else hi2 = mid; }
        n1 = qi + 1;
        n2 = lo2 - tstart;
    } else {
        n1 = target;
        n2 = qi - tstart + 1;
    }
    int n = n1 + n2;
    __syncthreads();

    const float4* q4 = (const float4*)shq;
    for (int j = tid; j < n; j += 64) {
        const float* kv = (j < n1)
            ? qkvS + ((size_t)(b * NBAR + j)) * QKVLD + 512 + h * DHH
            : qkvR + ((size_t)(b * SS + tstart + (j - n1))) * QKVLD + 512 + h * DHH;
        const float4* k4 = (const float4*)kv;
        float acc = 0.0f;
        #pragma unroll
        for (int d = 0; d < DHH/4; d++) {
            float4 a = q4[d], kk = k4[d];
            acc += a.x*kk.x + a.y*kk.y + a.z*kk.z + a.w*kk.w;
        }
        sc[j] = acc * 0.125f;
    }
    __syncthreads();

    float mx = -1e30f;
    for (int j = tid; j < n; j += 64) mx = fmaxf(mx, sc[j]);
    red[tid] = mx; __syncthreads();
    for (int o = 32; o > 0; o >>= 1) { if (tid < o) red[tid] = fmaxf(red[tid], red[tid+o]); __syncthreads(); }
    mx = red[0]; __syncthreads();

    float sm = 0.0f;
    for (int j = tid; j < n; j += 64) { float e = __expf(sc[j] - mx); sc[j] = e; sm += e; }
    red[tid] = sm; __syncthreads();
    for (int o = 32; o > 0; o >>= 1) { if (tid < o) red[tid] += red[tid+o]; __syncthreads(); }
    float invs = 1.0f / red[0];
    __syncthreads();

    float acc = 0.0f;
    for (int j = 0; j < n; j++) {
        const float* vv = (j < n1)
            ? qkvS + ((size_t)(b * NBAR + j)) * QKVLD + 1024 + h * DHH
            : qkvR + ((size_t)(b * SS + tstart + (j - n1))) * QKVLD + 1024 + h * DHH;
        acc += sc[j] * vv[tid];
    }
    O[(size_t)qrow * DD + h * DHH + tid] = acc * invs;
}

// ---------------------------------------------------------------------------
// Host side
// ---------------------------------------------------------------------------
static float* devptr(const void* sym) {
    void* p = nullptr;
    cudaGetSymbolAddress(&p, sym);
    return (float*)p;
}

static void gemm(const float* A, const float* A3, const float* B, float* C,
                 int M, int N, int K, bool transB, bool accum, bool swi) {
    dim3 grd(N / 128, M / 128);
    if (transB) {
        mma_gemm<1,0,0><<<grd, 256>>>(A, A3, B, C, M, N, K);
    } else if (swi) {
        mma_gemm<0,1,1><<<grd, 256>>>(A, A3, B, C, M, N, K);
    } else if (accum) {
        mma_gemm<0,1,0><<<grd, 256>>>(A, A3, B, C, M, N, K);
    } else {
        mma_gemm<0,0,0><<<grd, 256>>>(A, A3, B, C, M, N, K);
    }
}

extern "C" void kernel_launch(void* const* d_in, const int* in_sizes, int n_in,
                              void* d_out, int out_size) {
    const int* tok   = (const int*)d_in[0];
    const int* chord = (const int*)d_in[1];
    const int* inst  = (const int*)d_in[2];
    int o = (in_sizes[3] == 1) ? 4 : 3;
    const float* tok_emb  = (const float*)d_in[o + 0];
    const float* inst_emb = (const float*)d_in[o + 1];
    const float* bar_emb  = (const float*)d_in[o + 2];
    const float* ln_as_g  = (const float*)d_in[o + 3];
    const float* ln_as_b  = (const float*)d_in[o + 4];
    const float* ln_ar_g  = (const float*)d_in[o + 5];
    const float* ln_ar_b  = (const float*)d_in[o + 6];
    const float* ln_fs_g  = (const float*)d_in[o + 7];
    const float* ln_fs_b  = (const float*)d_in[o + 8];
    const float* ln_fr_g  = (const float*)d_in[o + 9];
    const float* ln_fr_b  = (const float*)d_in[o + 10];
    const float* Wq       = (const float*)d_in[o + 11];
    const float* Wk       = (const float*)d_in[o + 12];
    const float* Wv       = (const float*)d_in[o + 13];
    const float* Wo       = (const float*)d_in[o + 14];
    const float* fs_w1    = (const float*)d_in[o + 15];
    const float* fs_w3    = (const float*)d_in[o + 16];
    const float* fs_w2    = (const float*)d_in[o + 17];
    const float* fr_w1    = (const float*)d_in[o + 18];
    const float* fr_w3    = (const float*)d_in[o + 19];
    const float* fr_w2    = (const float*)d_in[o + 20];
    const float* out_g    = (const float*)d_in[o + 21];
    const float* out_b    = (const float*)d_in[o + 22];
    float* out = (float*)d_out;

    float* x    = devptr(g_x);
    float* sumx = devptr(g_sum);
    float* lnr  = devptr(g_lnr);
    float* lns  = devptr(g_lns);
    float* qkvr = devptr(g_qkvr);
    float* qkvs = devptr(g_qkvs);
    float* Or   = devptr(g_Or);
    float* Os   = devptr(g_Os);
    float* h1r  = devptr(g_h1r);
    float* h3r  = devptr(g_h3r);
    float* h1s  = devptr(g_h1s);
    float* h3s  = devptr(g_h3s);
    float* wqkv = devptr(g_wqkv);

    // Pack QKV weights (once per call; deterministic)
    pack_qkv_kernel<<<4096, 256>>>(Wq, Wk, Wv, wqkv);

    embed_kernel<<<RR, 128>>>(tok, inst, tok_emb, inst_emb, x);
    sum_init_kernel<<<SRR, 128>>>(bar_emb, sumx);

    for (int l = 0; l < LL; l++) {
        const float* wqkv_l = wqkv + (size_t)l * DD * 3 * DD;
        const float* wo     = Wo   + (size_t)l * DD * DD;

        // --- attention ---
        ln_kernel<<<SRR, 256>>>(sumx, ln_as_g + l*DD, ln_as_b + l*DD, lns);
        ln_kernel<<<RR,  256>>>(x,    ln_ar_g + l*DD, ln_ar_b + l*DD, lnr);

        gemm(lns, nullptr, wqkv_l, qkvs, SRR, 3*DD, DD, false, false, false);
        gemm(lnr, nullptr, wqkv_l, qkvr, RR,  3*DD, DD, false, false, false);

        rope_kernel<<<(SRR*512 + 255)/256, 256>>>(qkvs, SRR, NBAR);
        rope_kernel<<<(RR*512  + 255)/256, 256>>>(qkvr, RR,  SS);

        attn_kernel<1><<<dim3(SRR, HH), 64>>>(qkvs, qkvr, chord, Os);
        attn_kernel<0><<<dim3(RR,  HH), 64>>>(qkvs, qkvr, chord, Or);

        gemm(Os, nullptr, wo, sumx, SRR, DD, DD, false, true, false);
        gemm(Or, nullptr, wo, x,    RR,  DD, DD, false, true, false);

        // --- FFN ---
        ln_kernel<<<SRR, 256>>>(sumx, ln_fs_g + l*DD, ln_fs_b + l*DD, lns);
        ln_kernel<<<RR,  256>>>(x,    ln_fr_g + l*DD, ln_fr_b + l*DD, lnr);

        gemm(lns, nullptr, fs_w1 + (size_t)l*DD*FF, h1s, SRR, FF, DD, false, false, false);
        gemm(lns, nullptr, fs_w3 + (size_t)l*DD*FF, h3s, SRR, FF, DD, false, false, false);
        gemm(lnr, nullptr, fr_w1 + (size_t)l*DD*FF, h1r, RR,  FF, DD, false, false, false);
        gemm(lnr, nullptr, fr_w3 + (size_t)l*DD*FF, h3r, RR,  FF, DD, false, false, false);

        // w2 with fused swiglu on A
        gemm(h1s, h3s, fs_w2 + (size_t)l*FF*DD, sumx, SRR, DD, FF, false, true, true);
        gemm(h1r, h3r, fr_w2 + (size_t)l*FF*DD, x,    RR,  DD, FF, false, true, true);
    }

    ln_kernel<<<RR, 256>>>(x, out_g, out_b, lnr);
    gemm(lnr, nullptr, tok_emb, out, RR, VV, DD, true, false, false);
}

// round 9
// speedup vs baseline: 1.1363x; 1.1363x over previous
#include <cuda_runtime.h>
#include <cuda_bf16.h>
#include <math.h>

// ---------------------------------------------------------------------------
// Problem constants
// ---------------------------------------------------------------------------
#define BB   2
#define SS   1024
#define NBAR 64
#define DD   512
#define HH   8
#define DHH  64
#define FF   2048
#define LL   12
#define VV   1024

#define RR   (BB*SS)      // 2048
#define SRR  (BB*NBAR)    // 128
#define KTOT (NBAR+SS)    // 1088
#define QKVLD 1536        // packed QKV row stride

// ---------------------------------------------------------------------------
// Device scratch
// ---------------------------------------------------------------------------
__device__ float g_x    [RR*DD];
__device__ float g_sum  [SRR*DD];
__device__ float g_lnr  [RR*DD];
__device__ float g_lns  [SRR*DD];
__device__ float g_qkvr [RR*QKVLD];
__device__ float g_qkvs [SRR*QKVLD];
__device__ float g_Or   [RR*DD];
__device__ float g_Os   [SRR*DD];
__device__ float g_h1r  [RR*FF];
__device__ float g_h3r  [RR*FF];
__device__ float g_h1s  [SRR*FF];
__device__ float g_h3s  [SRR*FF];
__device__ float g_wqkv [LL*DD*3*DD];

// ---------------------------------------------------------------------------
// bf16 split helpers
// ---------------------------------------------------------------------------
__device__ __forceinline__ uint2 split_pack(float x0, float x1) {
    __nv_bfloat16 h0 = __float2bfloat16(x0);
    __nv_bfloat16 h1 = __float2bfloat16(x1);
    float r0 = x0 - __bfloat162float(h0);
    float r1 = x1 - __bfloat162float(h1);
    __nv_bfloat16 l0 = __float2bfloat16(r0);
    __nv_bfloat16 l1 = __float2bfloat16(r1);
    uint2 t;
    t.x = ((unsigned)__bfloat16_as_ushort(h1) << 16) | __bfloat16_as_ushort(h0);
    t.y = ((unsigned)__bfloat16_as_ushort(l1) << 16) | __bfloat16_as_ushort(l0);
    return t;
}

__device__ __forceinline__ void mma_bf16(float c[4],
                                         unsigned a0, unsigned a1, unsigned a2, unsigned a3,
                                         unsigned b0, unsigned b1) {
    asm volatile(
        "mma.sync.aligned.m16n8k16.row.col.f32.bf16.bf16.f32 "
        "{%0,%1,%2,%3}, {%4,%5,%6,%7}, {%8,%9}, {%0,%1,%2,%3};"
        : "+f"(c[0]), "+f"(c[1]), "+f"(c[2]), "+f"(c[3])
        : "r"(a0), "r"(a1), "r"(a2), "r"(a3), "r"(b0), "r"(b1));
}

__device__ __forceinline__ float silu(float x) {
    return x / (1.0f + __expf(-x));
}

// ---------------------------------------------------------------------------
// bf16x3 tensor-core GEMM.  C[M,N] = A[M,K] @ B  (B: KxN, or NxK if TRANSB)
// Block 128x64, BK=16, 256 threads, 8 warps at 32x32 each (2 CTAs/SM target).
// hi/lo interleaved uint2 smem (LDS.64 fragments); register prefetch of the
// next K-chunk hides GMEM latency.
// SWI: A := silu(A) * A3 applied during the A load (FFN w2 fusion).
// Requires M%128==0, N%64==0, K%16==0.
// ---------------------------------------------------------------------------
#define AMP 132
#define BNP 68

template<int TRANSB, int ACC, int SWI>
__global__ void __launch_bounds__(256, 2)
mma_gemm(const float* __restrict__ A, const float* __restrict__ A3,
         const float* __restrict__ B, float* __restrict__ C,
         int M, int N, int K) {
    __shared__ uint2 As[8 * AMP];
    __shared__ uint2 Bs[8 * BNP];

    int tid = threadIdx.x;
    int m0 = blockIdx.y * 128, n0 = blockIdx.x * 64;
    int wid = tid >> 5, lane = tid & 31;
    int wm = (wid >> 1) * 32, wn = (wid & 1) * 32;
    int g = lane >> 2, tig = lane & 3;

    // A loader: row = tid>>1 (0..127), k-segment 0 or 8 -> pairs p0..p0+3
    int arow = tid >> 1, aseg = (tid & 1) * 8;
    int p0 = (tid & 1) * 4;
    // B no-trans loader: col = tid&63, pair group (tid>>6)*2 -> 2 pairs
    int bn = tid & 63, pgrp = (tid >> 6) * 2;
    // B trans loader: row(n) = tid>>2 (0..63), k-segment (tid&3)*4 -> 2 pairs
    int brow = tid >> 2, bseg = (tid & 3) * 4;
    int bp0 = (tid & 3) * 2;

    const float* Aptr  = A + (size_t)(m0 + arow) * K + aseg;
    const float* A3ptr = SWI ? (A3 + (size_t)(m0 + arow) * K + aseg) : A;
    const float* Btr   = TRANSB ? (B + (size_t)(n0 + brow) * K + bseg) : B;
    const float* Bnt   = TRANSB ? B : (B + n0 + bn);

    float4 la0, la1, la30, la31, lbt;
    float lb[4];

    // prologue: chunk 0
    la0 = *(const float4*)(Aptr);
    la1 = *(const float4*)(Aptr + 4);
    if (SWI) { la30 = *(const float4*)(A3ptr); la31 = *(const float4*)(A3ptr + 4); }
    if (TRANSB) {
        lbt = *(const float4*)(Btr);
    } else {
        #pragma unroll
        for (int pp = 0; pp < 2; pp++) {
            lb[2*pp+0] = Bnt[(size_t)(2*(pgrp+pp)  ) * N];
            lb[2*pp+1] = Bnt[(size_t)(2*(pgrp+pp)+1) * N];
        }
    }

    float c[2][4][4] = {};

    for (int k0 = 0; k0 < K; k0 += 16) {
        // ---- stage current chunk into smem ----
        float4 va0 = la0, va1 = la1;
        if (SWI) {
            va0.x = silu(va0.x) * la30.x; va0.y = silu(va0.y) * la30.y;
            va0.z = silu(va0.z) * la30.z; va0.w = silu(va0.w) * la30.w;
            va1.x = silu(va1.x) * la31.x; va1.y = silu(va1.y) * la31.y;
            va1.z = silu(va1.z) * la31.z; va1.w = silu(va1.w) * la31.w;
        }
        As[(p0+0)*AMP + arow] = split_pack(va0.x, va0.y);
        As[(p0+1)*AMP + arow] = split_pack(va0.z, va0.w);
        As[(p0+2)*AMP + arow] = split_pack(va1.x, va1.y);
        As[(p0+3)*AMP + arow] = split_pack(va1.z, va1.w);
        if (TRANSB) {
            Bs[(bp0+0)*BNP + brow] = split_pack(lbt.x, lbt.y);
            Bs[(bp0+1)*BNP + brow] = split_pack(lbt.z, lbt.w);
        } else {
            Bs[(pgrp+0)*BNP + bn] = split_pack(lb[0], lb[1]);
            Bs[(pgrp+1)*BNP + bn] = split_pack(lb[2], lb[3]);
        }
        __syncthreads();

        // ---- prefetch next chunk into registers ----
        if (k0 + 16 < K) {
            la0 = *(const float4*)(Aptr + k0 + 16);
            la1 = *(const float4*)(Aptr + k0 + 20);
            if (SWI) {
                la30 = *(const float4*)(A3ptr + k0 + 16);
                la31 = *(const float4*)(A3ptr + k0 + 20);
            }
            if (TRANSB) {
                lbt = *(const float4*)(Btr + k0 + 16);
            } else {
                #pragma unroll
                for (int pp = 0; pp < 2; pp++) {
                    lb[2*pp+0] = Bnt[(size_t)(k0 + 16 + 2*(pgrp+pp)  ) * N];
                    lb[2*pp+1] = Bnt[(size_t)(k0 + 16 + 2*(pgrp+pp)+1) * N];
                }
            }
        }

        // ---- compute ----
        uint2 af[2][4];
        #pragma unroll
        for (int mt = 0; mt < 2; mt++) {
            int mr = wm + mt * 16 + g;
            af[mt][0] = As[(tig  )*AMP + mr];
            af[mt][1] = As[(tig  )*AMP + mr + 8];
            af[mt][2] = As[(tig+4)*AMP + mr];
            af[mt][3] = As[(tig+4)*AMP + mr + 8];
        }
        uint2 bf[4][2];
        #pragma unroll
        for (int nt = 0; nt < 4; nt++) {
            int nc = wn + nt * 8 + g;
            bf[nt][0] = Bs[(tig  )*BNP + nc];
            bf[nt][1] = Bs[(tig+4)*BNP + nc];
        }
        #pragma unroll
        for (int mt = 0; mt < 2; mt++)
            #pragma unroll
            for (int nt = 0; nt < 4; nt++) {
                mma_bf16(c[mt][nt], af[mt][0].x, af[mt][1].x, af[mt][2].x, af[mt][3].x,
                         bf[nt][0].x, bf[nt][1].x);
                mma_bf16(c[mt][nt], af[mt][0].x, af[mt][1].x, af[mt][2].x, af[mt][3].x,
                         bf[nt][0].y, bf[nt][1].y);
                mma_bf16(c[mt][nt], af[mt][0].y, af[mt][1].y, af[mt][2].y, af[mt][3].y,
                         bf[nt][0].x, bf[nt][1].x);
            }
        __syncthreads();
    }

    #pragma unroll
    for (int mt = 0; mt < 2; mt++) {
        #pragma unroll
        for (int r = 0; r < 2; r++) {
            int row = m0 + wm + mt * 16 + g + r * 8;
            #pragma unroll
            for (int nt = 0; nt < 4; nt++) {
                int col = n0 + wn + nt * 8 + tig * 2;
                float2* cp = (float2*)(C + (size_t)row * N + col);
                float v0 = c[mt][nt][r*2+0], v1 = c[mt][nt][r*2+1];
                if (ACC) {
                    float2 o = *cp; o.x += v0; o.y += v1; *cp = o;
                } else {
                    float2 o; o.x = v0; o.y = v1; *cp = o;
                }
            }
        }
    }
}

// ---------------------------------------------------------------------------
// QKV weight packing: wqkv[l][k][0:512]=Wq, [512:1024]=Wk, [1024:1536]=Wv
// ---------------------------------------------------------------------------
__global__ void pack_qkv_kernel(const float* __restrict__ Wq,
                                const float* __restrict__ Wk,
                                const float* __restrict__ Wv,
                                float* __restrict__ out) {
    int total = LL * DD * 3 * DD;
    for (int idx = blockIdx.x * blockDim.x + threadIdx.x; idx < total;
         idx += gridDim.x * blockDim.x) {
        int j = idx % (3*DD);
        int rest = idx / (3*DD);
        float v;
        if (j < DD)            v = Wq[(size_t)rest * DD + j];
        else if (j < 2*DD)     v = Wk[(size_t)rest * DD + (j - DD)];
        else                   v = Wv[(size_t)rest * DD + (j - 2*DD)];
        out[idx] = v;
    }
}

// ---------------------------------------------------------------------------
// Embedding init
// ---------------------------------------------------------------------------
__global__ void embed_kernel(const int* __restrict__ tok,
                             const int* __restrict__ inst,
                             const float* __restrict__ tok_emb,
                             const float* __restrict__ inst_emb,
                             float* __restrict__ x) {
    int row = blockIdx.x;
    int t = tok[row];
    int ii = inst[row]; ii = ii < 0 ? 0 : (ii > 129 ? 129 : ii);
    const float4* te = (const float4*)(tok_emb  + (size_t)t  * DD);
    const float4* ie = (const float4*)(inst_emb + (size_t)ii * DD);
    float4* xo = (float4*)(x + (size_t)row * DD);
    for (int d = threadIdx.x; d < DD/4; d += blockDim.x) {
        float4 a = te[d], b = ie[d];
        xo[d] = make_float4(a.x+b.x, a.y+b.y, a.z+b.z, a.w+b.w);
    }
}

__global__ void sum_init_kernel(const float* __restrict__ bar_emb,
                                float* __restrict__ sum_x) {
    int row = blockIdx.x;
    int bar = row % NBAR;
    const float4* be = (const float4*)(bar_emb + (size_t)bar * DD);
    float4* so = (float4*)(sum_x + (size_t)row * DD);
    for (int d = threadIdx.x; d < DD/4; d += blockDim.x) so[d] = be[d];
}

// ---------------------------------------------------------------------------
// LayerNorm
// ---------------------------------------------------------------------------
__global__ void __launch_bounds__(256)
ln_kernel(const float* __restrict__ in,
          const float* __restrict__ g,
          const float* __restrict__ b,
          float* __restrict__ out) {
    int row = blockIdx.x;
    int tid = threadIdx.x;
    const float* xr = in + (size_t)row * DD;
    float v0 = xr[tid], v1 = xr[tid + 256];
    __shared__ float sh[256];
    sh[tid] = v0 + v1; __syncthreads();
    for (int o = 128; o > 0; o >>= 1) { if (tid < o) sh[tid] += sh[tid+o]; __syncthreads(); }
    float mean = sh[0] * (1.0f/DD);
    __syncthreads();
    float d0 = v0 - mean, d1 = v1 - mean;
    sh[tid] = d0*d0 + d1*d1; __syncthreads();
    for (int o = 128; o > 0; o >>= 1) { if (tid < o) sh[tid] += sh[tid+o]; __syncthreads(); }
    float r = rsqrtf(sh[0] * (1.0f/DD) + 1e-5f);
    float* orow = out + (size_t)row * DD;
    orow[tid]       = d0 * r * g[tid]       + b[tid];
    orow[tid + 256] = d1 * r * g[tid + 256] + b[tid + 256];
}

// ---------------------------------------------------------------------------
// RoPE over packed QKV buffer: rotates head-slices 0..15 (Q + K heads),
// leaves V (cols 1024..1535) untouched.
// ---------------------------------------------------------------------------
__global__ void rope_kernel(float* __restrict__ buf, int rows, int posMod) {
    const float LOGF = 9.210340371976184f / 32.0f;
    int total = rows * 16 * 32;
    for (int idx = blockIdx.x * blockDim.x + threadIdx.x; idx < total;
         idx += gridDim.x * blockDim.x) {
        int row  = idx >> 9;
        int rem  = idx & 511;
        int head = rem >> 5;
        int d    = rem & 31;
        int pos  = row % posMod;
        float inv = __expf(-(float)d * LOGF);
        float f = (float)pos * inv;
        float c, s; __sincosf(f, &s, &c);
        float* p = buf + (size_t)row * QKVLD + head * 64;
        float x1 = p[d], x2 = p[d + 32];
        p[d]      = x1 * c - x2 * s;
        p[d + 32] = x1 * s + x2 * c;
    }
}

// ---------------------------------------------------------------------------
// Range-based sparse attention over packed QKV buffers.
// ---------------------------------------------------------------------------
template<int SUMQ>
__global__ void __launch_bounds__(64)
attn_kernel(const float* __restrict__ qkvS,
            const float* __restrict__ qkvR,
            const int*  __restrict__ chord,
            float* __restrict__ O) {
    const int QN = SUMQ ? NBAR : SS;
    int qrow = blockIdx.x;
    int h    = blockIdx.y;
    int tid  = threadIdx.x;
    int b    = qrow / QN;
    int qi   = qrow % QN;
    const int* ch = chord + b * SS;
    const float* qkvQ = SUMQ ? qkvS : qkvR;

    __shared__ float shq[DHH];
    __shared__ float sc[KTOT];
    __shared__ float red[64];

    if (tid < DHH) shq[tid] = qkvQ[(size_t)qrow * QKVLD + h * DHH + tid];

    int target = SUMQ ? qi : ch[qi];
    int lo = 0, hi = SS;
    while (lo < hi) { int mid = (lo + hi) >> 1; if (ch[mid] < target) lo = mid + 1; else hi = mid; }
    int tstart = lo;
    int n1, n2;
    if (SUMQ) {
        int lo2 = tstart, hi2 = SS;
        while (lo2 < hi2) { int mid = (lo2 + hi2) >> 1; if (ch[mid] < target + 1) lo2 = mid + 1; else hi2 = mid; }
        n1 = qi + 1;
        n2 = lo2 - tstart;
    } else {
        n1 = target;
        n2 = qi - tstart + 1;
    }
    int n = n1 + n2;
    __syncthreads();

    const float4* q4 = (const float4*)shq;
    for (int j = tid; j < n; j += 64) {
        const float* kv = (j < n1)
            ? qkvS + ((size_t)(b * NBAR + j)) * QKVLD + 512 + h * DHH
            : qkvR + ((size_t)(b * SS + tstart + (j - n1))) * QKVLD + 512 + h * DHH;
        const float4* k4 = (const float4*)kv;
        float acc = 0.0f;
        #pragma unroll
        for (int d = 0; d < DHH/4; d++) {
            float4 a = q4[d], kk = k4[d];
            acc += a.x*kk.x + a.y*kk.y + a.z*kk.z + a.w*kk.w;
        }
        sc[j] = acc * 0.125f;
    }
    __syncthreads();

    float mx = -1e30f;
    for (int j = tid; j < n; j += 64) mx = fmaxf(mx, sc[j]);
    red[tid] = mx; __syncthreads();
    for (int o = 32; o > 0; o >>= 1) { if (tid < o) red[tid] = fmaxf(red[tid], red[tid+o]); __syncthreads(); }
    mx = red[0]; __syncthreads();

    float sm = 0.0f;
    for (int j = tid; j < n; j += 64) { float e = __expf(sc[j] - mx); sc[j] = e; sm += e; }
    red[tid] = sm; __syncthreads();
    for (int o = 32; o > 0; o >>= 1) { if (tid < o) red[tid] += red[tid+o]; __syncthreads(); }
    float invs = 1.0f / red[0];
    __syncthreads();

    float acc = 0.0f;
    for (int j = 0; j < n; j++) {
        const float* vv = (j < n1)
            ? qkvS + ((size_t)(b * NBAR + j)) * QKVLD + 1024 + h * DHH
            : qkvR + ((size_t)(b * SS + tstart + (j - n1))) * QKVLD + 1024 + h * DHH;
        acc += sc[j] * vv[tid];
    }
    O[(size_t)qrow * DD + h * DHH + tid] = acc * invs;
}

// ---------------------------------------------------------------------------
// Host side
// ---------------------------------------------------------------------------
static float* devptr(const void* sym) {
    void* p = nullptr;
    cudaGetSymbolAddress(&p, sym);
    return (float*)p;
}

static void gemm(const float* A, const float* A3, const float* B, float* C,
                 int M, int N, int K, bool transB, bool accum, bool swi) {
    dim3 grd(N / 64, M / 128);
    if (transB) {
        mma_gemm<1,0,0><<<grd, 256>>>(A, A3, B, C, M, N, K);
    } else if (swi) {
        mma_gemm<0,1,1><<<grd, 256>>>(A, A3, B, C, M, N, K);
    } else if (accum) {
        mma_gemm<0,1,0><<<grd, 256>>>(A, A3, B, C, M, N, K);
    } else {
        mma_gemm<0,0,0><<<grd, 256>>>(A, A3, B, C, M, N, K);
    }
}

extern "C" void kernel_launch(void* const* d_in, const int* in_sizes, int n_in,
                              void* d_out, int out_size) {
    const int* tok   = (const int*)d_in[0];
    const int* chord = (const int*)d_in[1];
    const int* inst  = (const int*)d_in[2];
    int o = (in_sizes[3] == 1) ? 4 : 3;
    const float* tok_emb  = (const float*)d_in[o + 0];
    const float* inst_emb = (const float*)d_in[o + 1];
    const float* bar_emb  = (const float*)d_in[o + 2];
    const float* ln_as_g  = (const float*)d_in[o + 3];
    const float* ln_as_b  = (const float*)d_in[o + 4];
    const float* ln_ar_g  = (const float*)d_in[o + 5];
    const float* ln_ar_b  = (const float*)d_in[o + 6];
    const float* ln_fs_g  = (const float*)d_in[o + 7];
    const float* ln_fs_b  = (const float*)d_in[o + 8];
    const float* ln_fr_g  = (const float*)d_in[o + 9];
    const float* ln_fr_b  = (const float*)d_in[o + 10];
    const float* Wq       = (const float*)d_in[o + 11];
    const float* Wk       = (const float*)d_in[o + 12];
    const float* Wv       = (const float*)d_in[o + 13];
    const float* Wo       = (const float*)d_in[o + 14];
    const float* fs_w1    = (const float*)d_in[o + 15];
    const float* fs_w3    = (const float*)d_in[o + 16];
    const float* fs_w2    = (const float*)d_in[o + 17];
    const float* fr_w1    = (const float*)d_in[o + 18];
    const float* fr_w3    = (const float*)d_in[o + 19];
    const float* fr_w2    = (const float*)d_in[o + 20];
    const float* out_g    = (const float*)d_in[o + 21];
    const float* out_b    = (const float*)d_in[o + 22];
    float* out = (float*)d_out;

    float* x    = devptr(g_x);
    float* sumx = devptr(g_sum);
    float* lnr  = devptr(g_lnr);
    float* lns  = devptr(g_lns);
    float* qkvr = devptr(g_qkvr);
    float* qkvs = devptr(g_qkvs);
    float* Or   = devptr(g_Or);
    float* Os   = devptr(g_Os);
    float* h1r  = devptr(g_h1r);
    float* h3r  = devptr(g_h3r);
    float* h1s  = devptr(g_h1s);
    float* h3s  = devptr(g_h3s);
    float* wqkv = devptr(g_wqkv);

    pack_qkv_kernel<<<4096, 256>>>(Wq, Wk, Wv, wqkv);

    embed_kernel<<<RR, 128>>>(tok, inst, tok_emb, inst_emb, x);
    sum_init_kernel<<<SRR, 128>>>(bar_emb, sumx);

    for (int l = 0; l < LL; l++) {
        const float* wqkv_l = wqkv + (size_t)l * DD * 3 * DD;
        const float* wo     = Wo   + (size_t)l * DD * DD;

        // --- attention ---
        ln_kernel<<<SRR, 256>>>(sumx, ln_as_g + l*DD, ln_as_b + l*DD, lns);
        ln_kernel<<<RR,  256>>>(x,    ln_ar_g + l*DD, ln_ar_b + l*DD, lnr);

        gemm(lns, nullptr, wqkv_l, qkvs, SRR, 3*DD, DD, false, false, false);
        gemm(lnr, nullptr, wqkv_l, qkvr, RR,  3*DD, DD, false, false, false);

        rope_kernel<<<(SRR*512 + 255)/256, 256>>>(qkvs, SRR, NBAR);
        rope_kernel<<<(RR*512  + 255)/256, 256>>>(qkvr, RR,  SS);

        attn_kernel<1><<<dim3(SRR, HH), 64>>>(qkvs, qkvr, chord, Os);
        attn_kernel<0><<<dim3(RR,  HH), 64>>>(qkvs, qkvr, chord, Or);

        gemm(Os, nullptr, wo, sumx, SRR, DD, DD, false, true, false);
        gemm(Or, nullptr, wo, x,    RR,  DD, DD, false, true, false);

        // --- FFN ---
        ln_kernel<<<SRR, 256>>>(sumx, ln_fs_g + l*DD, ln_fs_b + l*DD, lns);
        ln_kernel<<<RR,  256>>>(x,    ln_fr_g + l*DD, ln_fr_b + l*DD, lnr);

        gemm(lns, nullptr, fs_w1 + (size_t)l*DD*FF, h1s, SRR, FF, DD, false, false, false);
        gemm(lns, nullptr, fs_w3 + (size_t)l*DD*FF, h3s, SRR, FF, DD, false, false, false);
        gemm(lnr, nullptr, fr_w1 + (size_t)l*DD*FF, h1r, RR,  FF, DD, false, false, false);
        gemm(lnr, nullptr, fr_w3 + (size_t)l*DD*FF, h3r, RR,  FF, DD, false, false, false);

        // w2 with fused swiglu on A
        gemm(h1s, h3s, fs_w2 + (size_t)l*FF*DD, sumx, SRR, DD, FF, false, true, true);
        gemm(h1r, h3r, fr_w2 + (size_t)l*FF*DD, x,    RR,  DD, FF, false, true, true);
    }

    ln_kernel<<<RR, 256>>>(x, out_g, out_b, lnr);
    gemm(lnr, nullptr, tok_emb, out, RR, VV, DD, true, false, false);
}

// round 11
// speedup vs baseline: 2.4477x; 2.1540x over previous
#include <cuda_runtime.h>
#include <cuda_bf16.h>
#include <math.h>

// ---------------------------------------------------------------------------
// Problem constants
// ---------------------------------------------------------------------------
#define BB   2
#define SS   1024
#define NBAR 64
#define DD   512
#define HH   8
#define DHH  64
#define FF   2048
#define LL   12
#define VV   1024

#define RR   (BB*SS)        // 2048
#define SRR  (BB*NBAR)      // 128
#define MALL (SRR+RR)       // 2176 = 17*128  (summary rows first)
#define DP   (DD/2)         // 256 k-pairs
#define FP   (FF/2)         // 1024 k-pairs
#define QKVLD 1536

// ---------------------------------------------------------------------------
// Device scratch (activations fp32; split operands as interleaved hi/lo uint2)
// ---------------------------------------------------------------------------
__device__ float g_xall[MALL*DD];                       // residual stream (sum rows 0..127)
__device__ __align__(16) uint2 g_ln  [MALL*DP];         // LN output, split
__device__ float g_qkv [MALL*QKVLD];                    // QKV projections fp32
__device__ __align__(16) uint2 g_Os  [MALL*DP];         // attention output, split
__device__ float g_h   [MALL*2*FF];                     // w1|w3 output fp32
__device__ __align__(16) uint2 g_hs  [MALL*FP];         // swiglu output, split
// pre-split weights
__device__ __align__(16) uint2 g_wqkv[LL*DP*1536];
__device__ __align__(16) uint2 g_wo  [LL*DP*DD];
__device__ __align__(16) uint2 g_w13s[LL*DP*2*FF];
__device__ __align__(16) uint2 g_w13r[LL*DP*2*FF];
__device__ __align__(16) uint2 g_w2s [LL*FP*DD];
__device__ __align__(16) uint2 g_w2r [LL*FP*DD];
__device__ __align__(16) uint2 g_tokT[DP*VV];

// ---------------------------------------------------------------------------
// bf16 split helpers
// ---------------------------------------------------------------------------
__device__ __forceinline__ uint2 split_pack(float x0, float x1) {
    __nv_bfloat16 h0 = __float2bfloat16(x0);
    __nv_bfloat16 h1 = __float2bfloat16(x1);
    float r0 = x0 - __bfloat162float(h0);
    float r1 = x1 - __bfloat162float(h1);
    __nv_bfloat16 l0 = __float2bfloat16(r0);
    __nv_bfloat16 l1 = __float2bfloat16(r1);
    uint2 t;
    t.x = ((unsigned)__bfloat16_as_ushort(h1) << 16) | __bfloat16_as_ushort(h0);
    t.y = ((unsigned)__bfloat16_as_ushort(l1) << 16) | __bfloat16_as_ushort(l0);
    return t;
}

__device__ __forceinline__ void mma_bf16(float c[4],
                                         unsigned a0, unsigned a1, unsigned a2, unsigned a3,
                                         unsigned b0, unsigned b1) {
    asm volatile(
        "mma.sync.aligned.m16n8k16.row.col.f32.bf16.bf16.f32 "
        "{%0,%1,%2,%3}, {%4,%5,%6,%7}, {%8,%9}, {%0,%1,%2,%3};"
        : "+f"(c[0]), "+f"(c[1]), "+f"(c[2]), "+f"(c[3])
        : "r"(a0), "r"(a1), "r"(a2), "r"(a3), "r"(b0), "r"(b1));
}

__device__ __forceinline__ float silu(float x) {
    return x / (1.0f + __expf(-x));
}

// ---------------------------------------------------------------------------
// Pure-bf16 GEMM on pre-split operands, cp.async 3-stage pipeline.
// A: [M][K/2] uint2 (hi|lo bf16x2 pairs along K), B: [K/2][N] uint2.
// C[M,N] fp32 (+= if ACC).  B0 used for blockIdx.y==0 (summary M-block),
// B1 otherwise.  Block 128x64, BK=16, 256 threads, warp tile 32x32.
// Requires M%128==0, N%64==0, K%16==0.
// ---------------------------------------------------------------------------
#define AP 10     // A smem row stride in uint2 (80B, 16B-aligned)
#define BP 68     // B smem row stride in uint2 (544B, 16B-aligned)
#define NSTG 3

template<int ACC>
__global__ void __launch_bounds__(256, 2)
gemm2(const uint2* __restrict__ A, const uint2* __restrict__ B0,
      const uint2* __restrict__ B1, float* __restrict__ C,
      int M, int N, int K) {
    __shared__ __align__(16) uint2 As[NSTG][128][AP];
    __shared__ __align__(16) uint2 Bs[NSTG][8][BP];

    const uint2* B = (blockIdx.y == 0) ? B0 : B1;
    int KP = K >> 1;
    int tid = threadIdx.x;
    int m0 = blockIdx.y * 128, n0 = blockIdx.x * 64;
    int wid = tid >> 5, lane = tid & 31;
    int wm = (wid >> 1) * 32, wn = (wid & 1) * 32;
    int g = lane >> 2, tig = lane & 3;

    // A loader: 2 x 16B per thread. transfer t -> row t>>2, 16B-seg t&3
    int ar0 = (tid*2)   >> 2, as0 = (tid*2)   & 3;
    int ar1 = (tid*2+1) >> 2, as1 = (tid*2+1) & 3;
    // B loader: 1 x 16B per thread. pair-row tid>>5, col-seg tid&31
    int br  = tid >> 5, bsg = tid & 31;

    auto issue = [&](int st, int ch) {
        {
            unsigned d = (unsigned)__cvta_generic_to_shared(&As[st][ar0][as0*2]);
            const uint2* s = A + (size_t)(m0 + ar0) * KP + ch*8 + as0*2;
            asm volatile("cp.async.cg.shared.global [%0], [%1], 16;\n" :: "r"(d), "l"(s));
        }
        {
            unsigned d = (unsigned)__cvta_generic_to_shared(&As[st][ar1][as1*2]);
            const uint2* s = A + (size_t)(m0 + ar1) * KP + ch*8 + as1*2;
            asm volatile("cp.async.cg.shared.global [%0], [%1], 16;\n" :: "r"(d), "l"(s));
        }
        {
            unsigned d = (unsigned)__cvta_generic_to_shared(&Bs[st][br][bsg*2]);
            const uint2* s = B + (size_t)(ch*8 + br) * N + n0 + bsg*2;
            asm volatile("cp.async.cg.shared.global [%0], [%1], 16;\n" :: "r"(d), "l"(s));
        }
        asm volatile("cp.async.commit_group;\n" ::);
    };

    int nch = K / 16;
    issue(0, 0);
    issue(1, 1);

    float c[2][4][4] = {};

    for (int ch = 0; ch < nch; ch++) {
        int st = ch % NSTG;
        // Drain: chunks ch..min(ch+1,nch-1) are committed; need chunk ch done.
        // While a younger group exists, allow 1 in flight; on the LAST chunk
        // only group ch is pending, so wait_group 0 is required (wait_group 1
        // would be a no-op -> race on the final stage).
        if (ch + 1 < nch) {
            asm volatile("cp.async.wait_group 1;\n" ::: "memory");
        } else {
            asm volatile("cp.async.wait_group 0;\n" ::: "memory");
        }
        __syncthreads();
        if (ch + 2 < nch) issue((ch + 2) % NSTG, ch + 2);

        uint2 af[2][4];
        #pragma unroll
        for (int mt = 0; mt < 2; mt++) {
            int mr = wm + mt * 16 + g;
            af[mt][0] = As[st][mr    ][tig];
            af[mt][1] = As[st][mr + 8][tig];
            af[mt][2] = As[st][mr    ][tig + 4];
            af[mt][3] = As[st][mr + 8][tig + 4];
        }
        uint2 bf[4][2];
        #pragma unroll
        for (int nt = 0; nt < 4; nt++) {
            int nc = wn + nt * 8 + g;
            bf[nt][0] = Bs[st][tig    ][nc];
            bf[nt][1] = Bs[st][tig + 4][nc];
        }
        #pragma unroll
        for (int mt = 0; mt < 2; mt++)
            #pragma unroll
            for (int nt = 0; nt < 4; nt++) {
                mma_bf16(c[mt][nt], af[mt][0].x, af[mt][1].x, af[mt][2].x, af[mt][3].x,
                         bf[nt][0].x, bf[nt][1].x);
                mma_bf16(c[mt][nt], af[mt][0].x, af[mt][1].x, af[mt][2].x, af[mt][3].x,
                         bf[nt][0].y, bf[nt][1].y);
                mma_bf16(c[mt][nt], af[mt][0].y, af[mt][1].y, af[mt][2].y, af[mt][3].y,
                         bf[nt][0].x, bf[nt][1].x);
            }
        __syncthreads();
    }

    #pragma unroll
    for (int mt = 0; mt < 2; mt++) {
        #pragma unroll
        for (int r = 0; r < 2; r++) {
            int row = m0 + wm + mt * 16 + g + r * 8;
            #pragma unroll
            for (int nt = 0; nt < 4; nt++) {
                int col = n0 + wn + nt * 8 + tig * 2;
                float2* cp = (float2*)(C + (size_t)row * N + col);
                float v0 = c[mt][nt][r*2+0], v1 = c[mt][nt][r*2+1];
                if (ACC) { float2 o = *cp; o.x += v0; o.y += v1; *cp = o; }
                else     { float2 o; o.x = v0; o.y = v1; *cp = o; }
            }
        }
    }
}

// ---------------------------------------------------------------------------
// Weight pre-split: src fp32 [L][K][N] -> dst uint2 [L][K/2][DN] at col offset.
// ---------------------------------------------------------------------------
__global__ void pack_w(const float* __restrict__ src, uint2* __restrict__ dst,
                       int L, int K, int N, int DN, int coff) {
    int KP = K / 2;
    long total = (long)L * KP * N;
    for (long i = blockIdx.x * (long)blockDim.x + threadIdx.x; i < total;
         i += (long)gridDim.x * blockDim.x) {
        int n = (int)(i % N);
        long t = i / N;
        int kp = (int)(t % KP);
        int l  = (int)(t / KP);
        float a = src[((long)l*K + 2*kp    )*N + n];
        float b = src[((long)l*K + 2*kp + 1)*N + n];
        dst[((long)l*KP + kp)*DN + coff + n] = split_pack(a, b);
    }
}

// tok_emb [V][D] -> [D/2][V] pair layout (for logits B)
__global__ void pack_tok(const float* __restrict__ tok, uint2* __restrict__ dst) {
    int total = DP * VV;
    for (int i = blockIdx.x * blockDim.x + threadIdx.x; i < total;
         i += gridDim.x * blockDim.x) {
        int v = i % VV, kp = i / VV;
        dst[kp * VV + v] = split_pack(tok[(size_t)v*DD + 2*kp], tok[(size_t)v*DD + 2*kp + 1]);
    }
}

// ---------------------------------------------------------------------------
// Embedding init into the combined residual buffer
// ---------------------------------------------------------------------------
__global__ void embed_kernel(const int* __restrict__ tok,
                             const int* __restrict__ inst,
                             const float* __restrict__ tok_emb,
                             const float* __restrict__ inst_emb,
                             float* __restrict__ xall) {
    int row = blockIdx.x;                  // 0..RR-1
    int t = tok[row];
    int ii = inst[row]; ii = ii < 0 ? 0 : (ii > 129 ? 129 : ii);
    const float4* te = (const float4*)(tok_emb  + (size_t)t  * DD);
    const float4* ie = (const float4*)(inst_emb + (size_t)ii * DD);
    float4* xo = (float4*)(xall + (size_t)(SRR + row) * DD);
    for (int d = threadIdx.x; d < DD/4; d += blockDim.x) {
        float4 a = te[d], b = ie[d];
        xo[d] = make_float4(a.x+b.x, a.y+b.y, a.z+b.z, a.w+b.w);
    }
}

__global__ void sum_init_kernel(const float* __restrict__ bar_emb,
                                float* __restrict__ xall) {
    int row = blockIdx.x;                  // 0..SRR-1
    int bar = row % NBAR;
    const float4* be = (const float4*)(bar_emb + (size_t)bar * DD);
    float4* so = (float4*)(xall + (size_t)row * DD);
    for (int d = threadIdx.x; d < DD/4; d += blockDim.x) so[d] = be[d];
}

// ---------------------------------------------------------------------------
// LayerNorm over 2176 combined rows; per-row param select; emits split form.
// ---------------------------------------------------------------------------
__global__ void __launch_bounds__(256)
ln_split(const float* __restrict__ in,
         const float* __restrict__ gS, const float* __restrict__ bS,
         const float* __restrict__ gR, const float* __restrict__ bR,
         uint2* __restrict__ out) {
    int row = blockIdx.x;
    int tid = threadIdx.x;
    const float* gg = (row < SRR) ? gS : gR;
    const float* bb = (row < SRR) ? bS : bR;
    const float2* xr = (const float2*)(in + (size_t)row * DD);
    float2 v = xr[tid];
    __shared__ float sh[256];
    sh[tid] = v.x + v.y; __syncthreads();
    for (int o = 128; o > 0; o >>= 1) { if (tid < o) sh[tid] += sh[tid+o]; __syncthreads(); }
    float mean = sh[0] * (1.0f/DD);
    __syncthreads();
    float d0 = v.x - mean, d1 = v.y - mean;
    sh[tid] = d0*d0 + d1*d1; __syncthreads();
    for (int o = 128; o > 0; o >>= 1) { if (tid < o) sh[tid] += sh[tid+o]; __syncthreads(); }
    float r = rsqrtf(sh[0] * (1.0f/DD) + 1e-5f);
    float y0 = d0 * r * gg[2*tid]   + bb[2*tid];
    float y1 = d1 * r * gg[2*tid+1] + bb[2*tid+1];
    out[(size_t)row * DP + tid] = split_pack(y0, y1);
}

// ---------------------------------------------------------------------------
// RoPE over combined QKV buffer (heads 0..15 = Q+K); V untouched.
// ---------------------------------------------------------------------------
__global__ void rope2(float* __restrict__ buf) {
    const float LOGF = 9.210340371976184f / 32.0f;
    int total = MALL * 16 * 32;
    for (int idx = blockIdx.x * blockDim.x + threadIdx.x; idx < total;
         idx += gridDim.x * blockDim.x) {
        int row  = idx >> 9;
        int rem  = idx & 511;
        int head = rem >> 5;
        int d    = rem & 31;
        int pos  = (row < SRR) ? (row & (NBAR-1)) : ((row - SRR) & (SS-1));
        float inv = __expf(-(float)d * LOGF);
        float f = (float)pos * inv;
        float c, s; __sincosf(f, &s, &c);
        float* p = buf + (size_t)row * QKVLD + head * 64;
        float x1 = p[d], x2 = p[d + 32];
        p[d]      = x1 * c - x2 * s;
        p[d + 32] = x1 * s + x2 * c;
    }
}

// ---------------------------------------------------------------------------
// Merged range-sparse attention over combined rows; emits split output.
// ---------------------------------------------------------------------------
__global__ void __launch_bounds__(64)
attn2(const float* __restrict__ qkv, const int* __restrict__ chord,
      uint2* __restrict__ O) {
    int qrow = blockIdx.x;
    int h    = blockIdx.y;
    int tid  = threadIdx.x;
    bool sum = qrow < SRR;
    int b, qi;
    if (sum) { b = qrow / NBAR; qi = qrow % NBAR; }
    else     { int r = qrow - SRR; b = r / SS; qi = r % SS; }
    const int* ch = chord + b * SS;

    __shared__ float shq[DHH];
    __shared__ float sc[NBAR + SS];
    __shared__ float red[64];

    shq[tid] = qkv[(size_t)qrow * QKVLD + h * DHH + tid];

    int target = sum ? qi : ch[qi];
    int lo = 0, hi = SS;
    while (lo < hi) { int mid = (lo + hi) >> 1; if (ch[mid] < target) lo = mid + 1; else hi = mid; }
    int tstart = lo;
    int n1, n2;
    if (sum) {
        int lo2 = tstart, hi2 = SS;
        while (lo2 < hi2) { int mid = (lo2 + hi2) >> 1; if (ch[mid] < target + 1) lo2 = mid + 1; else hi2 = mid; }
        n1 = qi + 1;
        n2 = lo2 - tstart;
    } else {
        n1 = target;
        n2 = qi - tstart + 1;
    }
    int n = n1 + n2;
    __syncthreads();

    const float4* q4 = (const float4*)shq;
    for (int j = tid; j < n; j += 64) {
        int krow = (j < n1) ? (b * NBAR + j) : (SRR + b * SS + tstart + (j - n1));
        const float4* k4 = (const float4*)(qkv + (size_t)krow * QKVLD + 512 + h * DHH);
        float acc = 0.0f;
        #pragma unroll
        for (int d = 0; d < DHH/4; d++) {
            float4 a = q4[d], kk = k4[d];
            acc += a.x*kk.x + a.y*kk.y + a.z*kk.z + a.w*kk.w;
        }
        sc[j] = acc * 0.125f;
    }
    __syncthreads();

    float mx = -1e30f;
    for (int j = tid; j < n; j += 64) mx = fmaxf(mx, sc[j]);
    red[tid] = mx; __syncthreads();
    for (int o = 32; o > 0; o >>= 1) { if (tid < o) red[tid] = fmaxf(red[tid], red[tid+o]); __syncthreads(); }
    mx = red[0]; __syncthreads();

    float sm = 0.0f;
    for (int j = tid; j < n; j += 64) { float e = __expf(sc[j] - mx); sc[j] = e; sm += e; }
    red[tid] = sm; __syncthreads();
    for (int o = 32; o > 0; o >>= 1) { if (tid < o) red[tid] += red[tid+o]; __syncthreads(); }
    float invs = 1.0f / red[0];
    __syncthreads();

    float acc = 0.0f;
    for (int j = 0; j < n; j++) {
        int vrow = (j < n1) ? (b * NBAR + j) : (SRR + b * SS + tstart + (j - n1));
        acc += sc[j] * qkv[(size_t)vrow * QKVLD + 1024 + h * DHH + tid];
    }
    red[tid] = acc * invs;
    __syncthreads();
    if (tid < 32)
        O[(size_t)qrow * DP + h * 32 + tid] = split_pack(red[2*tid], red[2*tid+1]);
}

// ---------------------------------------------------------------------------
// SwiGLU on w1|w3 output; emits split form.
// ---------------------------------------------------------------------------
__global__ void swiglu_split(const float* __restrict__ hall, uint2* __restrict__ out) {
    int total = MALL * FP;
    for (int i = blockIdx.x * blockDim.x + threadIdx.x; i < total;
         i += gridDim.x * blockDim.x) {
        int p = i % FP;
        int row = i / FP;
        const float* hr = hall + (size_t)row * (2*FF);
        float a0 = hr[2*p],      a1 = hr[2*p + 1];
        float b0 = hr[FF + 2*p], b1 = hr[FF + 2*p + 1];
        out[i] = split_pack(silu(a0) * b0, silu(a1) * b1);
    }
}

// ---------------------------------------------------------------------------
// Host side
// ---------------------------------------------------------------------------
static float* devptrf(const void* sym) {
    void* p = nullptr; cudaGetSymbolAddress(&p, sym); return (float*)p;
}
static uint2* devptru(const void* sym) {
    void* p = nullptr; cudaGetSymbolAddress(&p, sym); return (uint2*)p;
}

extern "C" void kernel_launch(void* const* d_in, const int* in_sizes, int n_in,
                              void* d_out, int out_size) {
    const int* tok   = (const int*)d_in[0];
    const int* chord = (const int*)d_in[1];
    const int* inst  = (const int*)d_in[2];
    int o = (in_sizes[3] == 1) ? 4 : 3;
    const float* tok_emb  = (const float*)d_in[o + 0];
    const float* inst_emb = (const float*)d_in[o + 1];
    const float* bar_emb  = (const float*)d_in[o + 2];
    const float* ln_as_g  = (const float*)d_in[o + 3];
    const float* ln_as_b  = (const float*)d_in[o + 4];
    const float* ln_ar_g  = (const float*)d_in[o + 5];
    const float* ln_ar_b  = (const float*)d_in[o + 6];
    const float* ln_fs_g  = (const float*)d_in[o + 7];
    const float* ln_fs_b  = (const float*)d_in[o + 8];
    const float* ln_fr_g  = (const float*)d_in[o + 9];
    const float* ln_fr_b  = (const float*)d_in[o + 10];
    const float* Wq       = (const float*)d_in[o + 11];
    const float* Wk       = (const float*)d_in[o + 12];
    const float* Wv       = (const float*)d_in[o + 13];
    const float* Wo       = (const float*)d_in[o + 14];
    const float* fs_w1    = (const float*)d_in[o + 15];
    const float* fs_w3    = (const float*)d_in[o + 16];
    const float* fs_w2    = (const float*)d_in[o + 17];
    const float* fr_w1    = (const float*)d_in[o + 18];
    const float* fr_w3    = (const float*)d_in[o + 19];
    const float* fr_w2    = (const float*)d_in[o + 20];
    const float* out_g    = (const float*)d_in[o + 21];
    const float* out_b    = (const float*)d_in[o + 22];
    float* out = (float*)d_out;

    float* xall = devptrf(g_xall);
    uint2* lnb  = devptru(g_ln);
    float* qkv  = devptrf(g_qkv);
    uint2* Ob   = devptru(g_Os);
    float* hall = devptrf(g_h);
    uint2* hs   = devptru(g_hs);
    uint2* wqkv = devptru(g_wqkv);
    uint2* wo   = devptru(g_wo);
    uint2* w13s = devptru(g_w13s);
    uint2* w13r = devptru(g_w13r);
    uint2* w2s  = devptru(g_w2s);
    uint2* w2r  = devptru(g_w2r);
    uint2* tokT = devptru(g_tokT);

    // ---- weight pre-split ----
    pack_w<<<4096, 256>>>(Wq, wqkv, LL, DD, DD, 1536, 0);
    pack_w<<<4096, 256>>>(Wk, wqkv, LL, DD, DD, 1536, 512);
    pack_w<<<4096, 256>>>(Wv, wqkv, LL, DD, DD, 1536, 1024);
    pack_w<<<4096, 256>>>(Wo, wo, LL, DD, DD, DD, 0);
    pack_w<<<4096, 256>>>(fs_w1, w13s, LL, DD, FF, 2*FF, 0);
    pack_w<<<4096, 256>>>(fs_w3, w13s, LL, DD, FF, 2*FF, FF);
    pack_w<<<4096, 256>>>(fr_w1, w13r, LL, DD, FF, 2*FF, 0);
    pack_w<<<4096, 256>>>(fr_w3, w13r, LL, DD, FF, 2*FF, FF);
    pack_w<<<4096, 256>>>(fs_w2, w2s, LL, FF, DD, DD, 0);
    pack_w<<<4096, 256>>>(fr_w2, w2r, LL, FF, DD, DD, 0);
    pack_tok<<<1024, 256>>>(tok_emb, tokT);

    // ---- embeddings ----
    embed_kernel<<<RR, 128>>>(tok, inst, tok_emb, inst_emb, xall);
    sum_init_kernel<<<SRR, 128>>>(bar_emb, xall);

    for (int l = 0; l < LL; l++) {
        uint2* wqkv_l = wqkv + (size_t)l * DP * 1536;
        uint2* wo_l   = wo   + (size_t)l * DP * DD;
        uint2* w13s_l = w13s + (size_t)l * DP * 2*FF;
        uint2* w13r_l = w13r + (size_t)l * DP * 2*FF;
        uint2* w2s_l  = w2s  + (size_t)l * FP * DD;
        uint2* w2r_l  = w2r  + (size_t)l * FP * DD;

        // --- attention ---
        ln_split<<<MALL, 256>>>(xall, ln_as_g + l*DD, ln_as_b + l*DD,
                                ln_ar_g + l*DD, ln_ar_b + l*DD, lnb);
        gemm2<0><<<dim3(1536/64, MALL/128), 256>>>(lnb, wqkv_l, wqkv_l, qkv, MALL, 1536, DD);
        rope2<<<2048, 256>>>(qkv);
        attn2<<<dim3(MALL, HH), 64>>>(qkv, chord, Ob);
        gemm2<1><<<dim3(DD/64, MALL/128), 256>>>(Ob, wo_l, wo_l, xall, MALL, DD, DD);

        // --- FFN ---
        ln_split<<<MALL, 256>>>(xall, ln_fs_g + l*DD, ln_fs_b + l*DD,
                                ln_fr_g + l*DD, ln_fr_b + l*DD, lnb);
        gemm2<0><<<dim3((2*FF)/64, MALL/128), 256>>>(lnb, w13s_l, w13r_l, hall, MALL, 2*FF, DD);
        swiglu_split<<<4096, 256>>>(hall, hs);
        gemm2<1><<<dim3(DD/64, MALL/128), 256>>>(hs, w2s_l, w2r_l, xall, MALL, DD, FF);
    }

    // final LN + logits on regular rows
    ln_split<<<MALL, 256>>>(xall, out_g, out_b, out_g, out_b, lnb);
    gemm2<0><<<dim3(VV/64, RR/128), 256>>>(lnb + (size_t)SRR * DP, tokT, tokT,
                                           out, RR, VV, DD);
}

// round 12
// speedup vs baseline: 2.4649x; 1.0070x over previous
#include <cuda_runtime.h>
#include <cuda_bf16.h>
#include <math.h>

// ---------------------------------------------------------------------------
// Problem constants
// ---------------------------------------------------------------------------
#define BB   2
#define SS   1024
#define NBAR 64
#define DD   512
#define HH   8
#define DHH  64
#define FF   2048
#define LL   12
#define VV   1024

#define RR   (BB*SS)        // 2048
#define SRR  (BB*NBAR)      // 128
#define MALL (SRR+RR)       // 2176 = 17*128  (summary rows first)
#define DP   (DD/2)         // 256 k-pairs
#define FP   (FF/2)         // 1024 k-pairs
#define QKVLD 1536

// ---------------------------------------------------------------------------
// Device scratch
// ---------------------------------------------------------------------------
__device__ float g_xall[MALL*DD];
__device__ __align__(16) uint2 g_ln  [MALL*DP];
__device__ float g_qkv [MALL*QKVLD];
__device__ __align__(16) uint2 g_Os  [MALL*DP];
__device__ float g_h   [MALL*2*FF];
__device__ __align__(16) uint2 g_hs  [MALL*FP];
__device__ __align__(16) uint2 g_wqkv[LL*DP*1536];
__device__ __align__(16) uint2 g_wo  [LL*DP*DD];
__device__ __align__(16) uint2 g_w13s[LL*DP*2*FF];
__device__ __align__(16) uint2 g_w13r[LL*DP*2*FF];
__device__ __align__(16) uint2 g_w2s [LL*FP*DD];
__device__ __align__(16) uint2 g_w2r [LL*FP*DD];
__device__ __align__(16) uint2 g_tokT[DP*VV];

// ---------------------------------------------------------------------------
// bf16 split helpers
// ---------------------------------------------------------------------------
__device__ __forceinline__ uint2 split_pack(float x0, float x1) {
    __nv_bfloat16 h0 = __float2bfloat16(x0);
    __nv_bfloat16 h1 = __float2bfloat16(x1);
    float r0 = x0 - __bfloat162float(h0);
    float r1 = x1 - __bfloat162float(h1);
    __nv_bfloat16 l0 = __float2bfloat16(r0);
    __nv_bfloat16 l1 = __float2bfloat16(r1);
    uint2 t;
    t.x = ((unsigned)__bfloat16_as_ushort(h1) << 16) | __bfloat16_as_ushort(h0);
    t.y = ((unsigned)__bfloat16_as_ushort(l1) << 16) | __bfloat16_as_ushort(l0);
    return t;
}

__device__ __forceinline__ void mma_bf16(float c[4],
                                         unsigned a0, unsigned a1, unsigned a2, unsigned a3,
                                         unsigned b0, unsigned b1) {
    asm volatile(
        "mma.sync.aligned.m16n8k16.row.col.f32.bf16.bf16.f32 "
        "{%0,%1,%2,%3}, {%4,%5,%6,%7}, {%8,%9}, {%0,%1,%2,%3};"
        : "+f"(c[0]), "+f"(c[1]), "+f"(c[2]), "+f"(c[3])
        : "r"(a0), "r"(a1), "r"(a2), "r"(a3), "r"(b0), "r"(b1));
}

__device__ __forceinline__ float silu(float x) {
    return x / (1.0f + __expf(-x));
}

// ---------------------------------------------------------------------------
// Pure-bf16 GEMM on pre-split operands, cp.async 4-stage pipeline (dyn smem).
// A: [M][K/2] uint2 (hi|lo bf16x2 pairs), B: [K/2][N] uint2.
// C[M,N] fp32 (+= if ACC).  B0 for blockIdx.y==0 (summary block), else B1.
// Block 128x64, BK=16, 256 threads, warp tile 32x32.
// ONE barrier per chunk: the leading __syncthreads at iter ch orders all
// reads of stage (ch-1)%NSTG before issue(ch+NSTG-1) overwrites it, and
// publishes chunk ch's cp.async data to all threads.
// ---------------------------------------------------------------------------
#define AP 10     // A smem row stride in uint2
#define BP 68     // B smem row stride in uint2
#define NSTG 4
#define GSMEM ((NSTG*128*AP + NSTG*8*BP) * (int)sizeof(uint2))   // 58368 B

template<int ACC>
__global__ void __launch_bounds__(256, 2)
gemm2(const uint2* __restrict__ A, const uint2* __restrict__ B0,
      const uint2* __restrict__ B1, float* __restrict__ C,
      int M, int N, int K) {
    extern __shared__ __align__(16) uint2 dyn[];
    uint2 (*As)[128][AP] = (uint2(*)[128][AP])dyn;
    uint2 (*Bs)[8][BP]   = (uint2(*)[8][BP])(dyn + NSTG*128*AP);

    const uint2* B = (blockIdx.y == 0) ? B0 : B1;
    int KP = K >> 1;
    int tid = threadIdx.x;
    int m0 = blockIdx.y * 128, n0 = blockIdx.x * 64;
    int wid = tid >> 5, lane = tid & 31;
    int wm = (wid >> 1) * 32, wn = (wid & 1) * 32;
    int g = lane >> 2, tig = lane & 3;

    int ar0 = (tid*2)   >> 2, as0 = (tid*2)   & 3;
    int ar1 = (tid*2+1) >> 2, as1 = (tid*2+1) & 3;
    int br  = tid >> 5, bsg = tid & 31;

    auto issue = [&](int st, int ch) {
        {
            unsigned d = (unsigned)__cvta_generic_to_shared(&As[st][ar0][as0*2]);
            const uint2* s = A + (size_t)(m0 + ar0) * KP + ch*8 + as0*2;
            asm volatile("cp.async.cg.shared.global [%0], [%1], 16;\n" :: "r"(d), "l"(s));
        }
        {
            unsigned d = (unsigned)__cvta_generic_to_shared(&As[st][ar1][as1*2]);
            const uint2* s = A + (size_t)(m0 + ar1) * KP + ch*8 + as1*2;
            asm volatile("cp.async.cg.shared.global [%0], [%1], 16;\n" :: "r"(d), "l"(s));
        }
        {
            unsigned d = (unsigned)__cvta_generic_to_shared(&Bs[st][br][bsg*2]);
            const uint2* s = B + (size_t)(ch*8 + br) * N + n0 + bsg*2;
            asm volatile("cp.async.cg.shared.global [%0], [%1], 16;\n" :: "r"(d), "l"(s));
        }
        asm volatile("cp.async.commit_group;\n" ::);
    };

    int nch = K / 16;          // >= 32 for all calls
    issue(0, 0);
    issue(1, 1);
    issue(2, 2);

    float c[2][4][4] = {};

    for (int ch = 0; ch < nch; ch++) {
        int st = ch & (NSTG - 1);
        // youngest committed group at this point is ch+2 (from prev iter).
        // chunk ch complete <=> pending-after-wait <= (#groups younger than ch).
        int rem = nch - 1 - ch;
        if (rem >= 2)      asm volatile("cp.async.wait_group 2;\n" ::: "memory");
        else if (rem == 1) asm volatile("cp.async.wait_group 1;\n" ::: "memory");
        else               asm volatile("cp.async.wait_group 0;\n" ::: "memory");
        __syncthreads();
        if (ch + 3 < nch) issue((ch + 3) & (NSTG - 1), ch + 3);

        uint2 af[2][4];
        #pragma unroll
        for (int mt = 0; mt < 2; mt++) {
            int mr = wm + mt * 16 + g;
            af[mt][0] = As[st][mr    ][tig];
            af[mt][1] = As[st][mr + 8][tig];
            af[mt][2] = As[st][mr    ][tig + 4];
            af[mt][3] = As[st][mr + 8][tig + 4];
        }
        uint2 bf[4][2];
        #pragma unroll
        for (int nt = 0; nt < 4; nt++) {
            int nc = wn + nt * 8 + g;
            bf[nt][0] = Bs[st][tig    ][nc];
            bf[nt][1] = Bs[st][tig + 4][nc];
        }
        #pragma unroll
        for (int mt = 0; mt < 2; mt++)
            #pragma unroll
            for (int nt = 0; nt < 4; nt++) {
                mma_bf16(c[mt][nt], af[mt][0].x, af[mt][1].x, af[mt][2].x, af[mt][3].x,
                         bf[nt][0].x, bf[nt][1].x);
                mma_bf16(c[mt][nt], af[mt][0].x, af[mt][1].x, af[mt][2].x, af[mt][3].x,
                         bf[nt][0].y, bf[nt][1].y);
                mma_bf16(c[mt][nt], af[mt][0].y, af[mt][1].y, af[mt][2].y, af[mt][3].y,
                         bf[nt][0].x, bf[nt][1].x);
            }
        // no trailing barrier: next iteration's leading barrier provides
        // both the WAR fence and cp.async data visibility.
    }

    #pragma unroll
    for (int mt = 0; mt < 2; mt++) {
        #pragma unroll
        for (int r = 0; r < 2; r++) {
            int row = m0 + wm + mt * 16 + g + r * 8;
            #pragma unroll
            for (int nt = 0; nt < 4; nt++) {
                int col = n0 + wn + nt * 8 + tig * 2;
                float2* cp = (float2*)(C + (size_t)row * N + col);
                float v0 = c[mt][nt][r*2+0], v1 = c[mt][nt][r*2+1];
                if (ACC) { float2 o = *cp; o.x += v0; o.y += v1; *cp = o; }
                else     { float2 o; o.x = v0; o.y = v1; *cp = o; }
            }
        }
    }
}

// ---------------------------------------------------------------------------
// Row-based weight pre-split: one block per (l,kp) output row.
// src fp32 [L][K][N] -> dst uint2 [L][K/2][DN] at column offset coff.
// ---------------------------------------------------------------------------
__global__ void pack_w_rows(const float* __restrict__ src, uint2* __restrict__ dst,
                            int K, int N, int DN, int coff) {
    int rowid = blockIdx.x;           // l*(K/2) + kp
    int KP = K >> 1;
    int kp = rowid % KP, l = rowid / KP;
    const float* s0 = src + ((long)l*K + 2*kp) * N;
    const float* s1 = s0 + N;
    uint2* d = dst + (long)rowid * DN + coff;
    for (int n = threadIdx.x; n < N; n += blockDim.x)
        d[n] = split_pack(s0[n], s1[n]);
}

// tok_emb [V][D] -> [D/2][V] pair layout (for logits B)
__global__ void pack_tok(const float* __restrict__ tok, uint2* __restrict__ dst) {
    int kp = blockIdx.x;              // 0..DP-1
    for (int v = threadIdx.x; v < VV; v += blockDim.x)
        dst[kp * VV + v] = split_pack(tok[(size_t)v*DD + 2*kp],
                                      tok[(size_t)v*DD + 2*kp + 1]);
}

// ---------------------------------------------------------------------------
// Embedding init into the combined residual buffer
// ---------------------------------------------------------------------------
__global__ void embed_kernel(const int* __restrict__ tok,
                             const int* __restrict__ inst,
                             const float* __restrict__ tok_emb,
                             const float* __restrict__ inst_emb,
                             float* __restrict__ xall) {
    int row = blockIdx.x;
    int t = tok[row];
    int ii = inst[row]; ii = ii < 0 ? 0 : (ii > 129 ? 129 : ii);
    const float4* te = (const float4*)(tok_emb  + (size_t)t  * DD);
    const float4* ie = (const float4*)(inst_emb + (size_t)ii * DD);
    float4* xo = (float4*)(xall + (size_t)(SRR + row) * DD);
    for (int d = threadIdx.x; d < DD/4; d += blockDim.x) {
        float4 a = te[d], b = ie[d];
        xo[d] = make_float4(a.x+b.x, a.y+b.y, a.z+b.z, a.w+b.w);
    }
}

__global__ void sum_init_kernel(const float* __restrict__ bar_emb,
                                float* __restrict__ xall) {
    int row = blockIdx.x;
    int bar = row % NBAR;
    const float4* be = (const float4*)(bar_emb + (size_t)bar * DD);
    float4* so = (float4*)(xall + (size_t)row * DD);
    for (int d = threadIdx.x; d < DD/4; d += blockDim.x) so[d] = be[d];
}

// ---------------------------------------------------------------------------
// LayerNorm over combined rows; per-row param select; emits split form.
// ---------------------------------------------------------------------------
__global__ void __launch_bounds__(256)
ln_split(const float* __restrict__ in,
         const float* __restrict__ gS, const float* __restrict__ bS,
         const float* __restrict__ gR, const float* __restrict__ bR,
         uint2* __restrict__ out) {
    int row = blockIdx.x;
    int tid = threadIdx.x;
    const float* gg = (row < SRR) ? gS : gR;
    const float* bb = (row < SRR) ? bS : bR;
    const float2* xr = (const float2*)(in + (size_t)row * DD);
    float2 v = xr[tid];
    __shared__ float sh[256];
    sh[tid] = v.x + v.y; __syncthreads();
    for (int o = 128; o > 0; o >>= 1) { if (tid < o) sh[tid] += sh[tid+o]; __syncthreads(); }
    float mean = sh[0] * (1.0f/DD);
    __syncthreads();
    float d0 = v.x - mean, d1 = v.y - mean;
    sh[tid] = d0*d0 + d1*d1; __syncthreads();
    for (int o = 128; o > 0; o >>= 1) { if (tid < o) sh[tid] += sh[tid+o]; __syncthreads(); }
    float r = rsqrtf(sh[0] * (1.0f/DD) + 1e-5f);
    float y0 = d0 * r * gg[2*tid]   + bb[2*tid];
    float y1 = d1 * r * gg[2*tid+1] + bb[2*tid+1];
    out[(size_t)row * DP + tid] = split_pack(y0, y1);
}

// ---------------------------------------------------------------------------
// RoPE over combined QKV buffer (heads 0..15 = Q+K); V untouched.
// ---------------------------------------------------------------------------
__global__ void rope2(float* __restrict__ buf) {
    const float LOGF = 9.210340371976184f / 32.0f;
    int total = MALL * 16 * 32;
    for (int idx = blockIdx.x * blockDim.x + threadIdx.x; idx < total;
         idx += gridDim.x * blockDim.x) {
        int row  = idx >> 9;
        int rem  = idx & 511;
        int head = rem >> 5;
        int d    = rem & 31;
        int pos  = (row < SRR) ? (row & (NBAR-1)) : ((row - SRR) & (SS-1));
        float inv = __expf(-(float)d * LOGF);
        float f = (float)pos * inv;
        float c, s; __sincosf(f, &s, &c);
        float* p = buf + (size_t)row * QKVLD + head * 64;
        float x1 = p[d], x2 = p[d + 32];
        p[d]      = x1 * c - x2 * s;
        p[d + 32] = x1 * s + x2 * c;
    }
}

// ---------------------------------------------------------------------------
// Merged range-sparse attention; emits split output.
// ---------------------------------------------------------------------------
__global__ void __launch_bounds__(64)
attn2(const float* __restrict__ qkv, const int* __restrict__ chord,
      uint2* __restrict__ O) {
    int qrow = blockIdx.x;
    int h    = blockIdx.y;
    int tid  = threadIdx.x;
    bool sum = qrow < SRR;
    int b, qi;
    if (sum) { b = qrow / NBAR; qi = qrow % NBAR; }
    else     { int r = qrow - SRR; b = r / SS; qi = r % SS; }
    const int* ch = chord + b * SS;

    __shared__ float shq[DHH];
    __shared__ float sc[NBAR + SS];
    __shared__ float red[64];

    shq[tid] = qkv[(size_t)qrow * QKVLD + h * DHH + tid];

    int target = sum ? qi : ch[qi];
    int lo = 0, hi = SS;
    while (lo < hi) { int mid = (lo + hi) >> 1; if (ch[mid] < target) lo = mid + 1; else hi = mid; }
    int tstart = lo;
    int n1, n2;
    if (sum) {
        int lo2 = tstart, hi2 = SS;
        while (lo2 < hi2) { int mid = (lo2 + hi2) >> 1; if (ch[mid] < target + 1) lo2 = mid + 1; else hi2 = mid; }
        n1 = qi + 1;
        n2 = lo2 - tstart;
    } else {
        n1 = target;
        n2 = qi - tstart + 1;
    }
    int n = n1 + n2;
    __syncthreads();

    const float4* q4 = (const float4*)shq;
    for (int j = tid; j < n; j += 64) {
        int krow = (j < n1) ? (b * NBAR + j) : (SRR + b * SS + tstart + (j - n1));
        const float4* k4 = (const float4*)(qkv + (size_t)krow * QKVLD + 512 + h * DHH);
        float acc = 0.0f;
        #pragma unroll
        for (int d = 0; d < DHH/4; d++) {
            float4 a = q4[d], kk = k4[d];
            acc += a.x*kk.x + a.y*kk.y + a.z*kk.z + a.w*kk.w;
        }
        sc[j] = acc * 0.125f;
    }
    __syncthreads();

    float mx = -1e30f;
    for (int j = tid; j < n; j += 64) mx = fmaxf(mx, sc[j]);
    red[tid] = mx; __syncthreads();
    for (int o = 32; o > 0; o >>= 1) { if (tid < o) red[tid] = fmaxf(red[tid], red[tid+o]); __syncthreads(); }
    mx = red[0]; __syncthreads();

    float sm = 0.0f;
    for (int j = tid; j < n; j += 64) { float e = __expf(sc[j] - mx); sc[j] = e; sm += e; }
    red[tid] = sm; __syncthreads();
    for (int o = 32; o > 0; o >>= 1) { if (tid < o) red[tid] += red[tid+o]; __syncthreads(); }
    float invs = 1.0f / red[0];
    __syncthreads();

    float acc = 0.0f;
    for (int j = 0; j < n; j++) {
        int vrow = (j < n1) ? (b * NBAR + j) : (SRR + b * SS + tstart + (j - n1));
        acc += sc[j] * qkv[(size_t)vrow * QKVLD + 1024 + h * DHH + tid];
    }
    red[tid] = acc * invs;
    __syncthreads();
    if (tid < 32)
        O[(size_t)qrow * DP + h * 32 + tid] = split_pack(red[2*tid], red[2*tid+1]);
}

// ---------------------------------------------------------------------------
// SwiGLU on w1|w3 output; emits split form.
// ---------------------------------------------------------------------------
__global__ void swiglu_split(const float* __restrict__ hall, uint2* __restrict__ out) {
    int total = MALL * FP;
    for (int i = blockIdx.x * blockDim.x + threadIdx.x; i < total;
         i += gridDim.x * blockDim.x) {
        int p = i % FP;
        int row = i / FP;
        const float* hr = hall + (size_t)row * (2*FF);
        float a0 = hr[2*p],      a1 = hr[2*p + 1];
        float b0 = hr[FF + 2*p], b1 = hr[FF + 2*p + 1];
        out[i] = split_pack(silu(a0) * b0, silu(a1) * b1);
    }
}

// ---------------------------------------------------------------------------
// Host side
// ---------------------------------------------------------------------------
static float* devptrf(const void* sym) {
    void* p = nullptr; cudaGetSymbolAddress(&p, sym); return (float*)p;
}
static uint2* devptru(const void* sym) {
    void* p = nullptr; cudaGetSymbolAddress(&p, sym); return (uint2*)p;
}

extern "C" void kernel_launch(void* const* d_in, const int* in_sizes, int n_in,
                              void* d_out, int out_size) {
    const int* tok   = (const int*)d_in[0];
    const int* chord = (const int*)d_in[1];
    const int* inst  = (const int*)d_in[2];
    int o = (in_sizes[3] == 1) ? 4 : 3;
    const float* tok_emb  = (const float*)d_in[o + 0];
    const float* inst_emb = (const float*)d_in[o + 1];
    const float* bar_emb  = (const float*)d_in[o + 2];
    const float* ln_as_g  = (const float*)d_in[o + 3];
    const float* ln_as_b  = (const float*)d_in[o + 4];
    const float* ln_ar_g  = (const float*)d_in[o + 5];
    const float* ln_ar_b  = (const float*)d_in[o + 6];
    const float* ln_fs_g  = (const float*)d_in[o + 7];
    const float* ln_fs_b  = (const float*)d_in[o + 8];
    const float* ln_fr_g  = (const float*)d_in[o + 9];
    const float* ln_fr_b  = (const float*)d_in[o + 10];
    const float* Wq       = (const float*)d_in[o + 11];
    const float* Wk       = (const float*)d_in[o + 12];
    const float* Wv       = (const float*)d_in[o + 13];
    const float* Wo       = (const float*)d_in[o + 14];
    const float* fs_w1    = (const float*)d_in[o + 15];
    const float* fs_w3    = (const float*)d_in[o + 16];
    const float* fs_w2    = (const float*)d_in[o + 17];
    const float* fr_w1    = (const float*)d_in[o + 18];
    const float* fr_w3    = (const float*)d_in[o + 19];
    const float* fr_w2    = (const float*)d_in[o + 20];
    const float* out_g    = (const float*)d_in[o + 21];
    const float* out_b    = (const float*)d_in[o + 22];
    float* out = (float*)d_out;

    float* xall = devptrf(g_xall);
    uint2* lnb  = devptru(g_ln);
    float* qkv  = devptrf(g_qkv);
    uint2* Ob   = devptru(g_Os);
    float* hall = devptrf(g_h);
    uint2* hs   = devptru(g_hs);
    uint2* wqkv = devptru(g_wqkv);
    uint2* wo   = devptru(g_wo);
    uint2* w13s = devptru(g_w13s);
    uint2* w13r = devptru(g_w13r);
    uint2* w2s  = devptru(g_w2s);
    uint2* w2r  = devptru(g_w2r);
    uint2* tokT = devptru(g_tokT);

    // allow 58.4KB dynamic smem on both gemm2 instantiations (idempotent)
    cudaFuncSetAttribute(gemm2<0>, cudaFuncAttributeMaxDynamicSharedMemorySize, GSMEM);
    cudaFuncSetAttribute(gemm2<1>, cudaFuncAttributeMaxDynamicSharedMemorySize, GSMEM);

    // ---- weight pre-split (row-based) ----
    pack_w_rows<<<LL*DP, 256>>>(Wq, wqkv, DD, DD, 1536, 0);
    pack_w_rows<<<LL*DP, 256>>>(Wk, wqkv, DD, DD, 1536, 512);
    pack_w_rows<<<LL*DP, 256>>>(Wv, wqkv, DD, DD, 1536, 1024);
    pack_w_rows<<<LL*DP, 256>>>(Wo, wo, DD, DD, DD, 0);
    pack_w_rows<<<LL*DP, 256>>>(fs_w1, w13s, DD, FF, 2*FF, 0);
    pack_w_rows<<<LL*DP, 256>>>(fs_w3, w13s, DD, FF, 2*FF, FF);
    pack_w_rows<<<LL*DP, 256>>>(fr_w1, w13r, DD, FF, 2*FF, 0);
    pack_w_rows<<<LL*DP, 256>>>(fr_w3, w13r, DD, FF, 2*FF, FF);
    pack_w_rows<<<LL*FP, 256>>>(fs_w2, w2s, FF, DD, DD, 0);
    pack_w_rows<<<LL*FP, 256>>>(fr_w2, w2r, FF, DD, DD, 0);
    pack_tok<<<DP, 256>>>(tok_emb, tokT);

    // ---- embeddings ----
    embed_kernel<<<RR, 128>>>(tok, inst, tok_emb, inst_emb, xall);
    sum_init_kernel<<<SRR, 128>>>(bar_emb, xall);

    for (int l = 0; l < LL; l++) {
        uint2* wqkv_l = wqkv + (size_t)l * DP * 1536;
        uint2* wo_l   = wo   + (size_t)l * DP * DD;
        uint2* w13s_l = w13s + (size_t)l * DP * 2*FF;
        uint2* w13r_l = w13r + (size_t)l * DP * 2*FF;
        uint2* w2s_l  = w2s  + (size_t)l * FP * DD;
        uint2* w2r_l  = w2r  + (size_t)l * FP * DD;

        // --- attention ---
        ln_split<<<MALL, 256>>>(xall, ln_as_g + l*DD, ln_as_b + l*DD,
                                ln_ar_g + l*DD, ln_ar_b + l*DD, lnb);
        gemm2<0><<<dim3(1536/64, MALL/128), 256, GSMEM>>>(lnb, wqkv_l, wqkv_l, qkv, MALL, 1536, DD);
        rope2<<<2048, 256>>>(qkv);
        attn2<<<dim3(MALL, HH), 64>>>(qkv, chord, Ob);
        gemm2<1><<<dim3(DD/64, MALL/128), 256, GSMEM>>>(Ob, wo_l, wo_l, xall, MALL, DD, DD);

        // --- FFN ---
        ln_split<<<MALL, 256>>>(xall, ln_fs_g + l*DD, ln_fs_b + l*DD,
                                ln_fr_g + l*DD, ln_fr_b + l*DD, lnb);
        gemm2<0><<<dim3((2*FF)/64, MALL/128), 256, GSMEM>>>(lnb, w13s_l, w13r_l, hall, MALL, 2*FF, DD);
        swiglu_split<<<4096, 256>>>(hall, hs);
        gemm2<1><<<dim3(DD/64, MALL/128), 256, GSMEM>>>(hs, w2s_l, w2r_l, xall, MALL, DD, FF);
    }

    // final LN + logits on regular rows
    ln_split<<<MALL, 256>>>(xall, out_g, out_b, out_g, out_b, lnb);
    gemm2<0><<<dim3(VV/64, RR/128), 256, GSMEM>>>(lnb + (size_t)SRR * DP, tokT, tokT,
                                                  out, RR, VV, DD);
}

// round 15
// speedup vs baseline: 2.5246x; 1.0242x over previous
#include <cuda_runtime.h>
#include <cuda_bf16.h>
#include <math.h>

// ---------------------------------------------------------------------------
// Problem constants
// ---------------------------------------------------------------------------
#define BB   2
#define SS   1024
#define NBAR 64
#define DD   512
#define HH   8
#define DHH  64
#define FF   2048
#define LL   12
#define VV   1024

#define RR   (BB*SS)        // 2048
#define SRR  (BB*NBAR)      // 128
#define MALL (SRR+RR)       // 2176 = 17*128  (summary rows first)
#define DP   (DD/2)         // 256 k-pairs
#define FP   (FF/2)         // 1024 k-pairs
#define QKVLD 1536
#define KTOT (NBAR+SS)      // 1088

// ---------------------------------------------------------------------------
// Device scratch (activations fp32; split operands as interleaved hi/lo uint2)
// ---------------------------------------------------------------------------
__device__ float g_xall[MALL*DD];
__device__ __align__(16) uint2 g_ln  [MALL*DP];
__device__ float g_qkv [MALL*QKVLD];
__device__ __align__(16) uint2 g_Os  [MALL*DP];
__device__ __align__(16) uint2 g_hs  [MALL*FP];
__device__ __align__(16) uint2 g_wqkv[LL*DP*1536];
__device__ __align__(16) uint2 g_wo  [LL*DP*DD];
__device__ __align__(16) uint2 g_w13s[LL*DP*2*FF];
__device__ __align__(16) uint2 g_w13r[LL*DP*2*FF];
__device__ __align__(16) uint2 g_w2s [LL*FP*DD];
__device__ __align__(16) uint2 g_w2r [LL*FP*DD];
__device__ __align__(16) uint2 g_tokT[DP*VV];

// ---------------------------------------------------------------------------
// bf16 split helpers
// ---------------------------------------------------------------------------
__device__ __forceinline__ uint2 split_pack(float x0, float x1) {
    __nv_bfloat16 h0 = __float2bfloat16(x0);
    __nv_bfloat16 h1 = __float2bfloat16(x1);
    float r0 = x0 - __bfloat162float(h0);
    float r1 = x1 - __bfloat162float(h1);
    __nv_bfloat16 l0 = __float2bfloat16(r0);
    __nv_bfloat16 l1 = __float2bfloat16(r1);
    uint2 t;
    t.x = ((unsigned)__bfloat16_as_ushort(h1) << 16) | __bfloat16_as_ushort(h0);
    t.y = ((unsigned)__bfloat16_as_ushort(l1) << 16) | __bfloat16_as_ushort(l0);
    return t;
}

__device__ __forceinline__ void mma_bf16(float c[4],
                                         unsigned a0, unsigned a1, unsigned a2, unsigned a3,
                                         unsigned b0, unsigned b1) {
    asm volatile(
        "mma.sync.aligned.m16n8k16.row.col.f32.bf16.bf16.f32 "
        "{%0,%1,%2,%3}, {%4,%5,%6,%7}, {%8,%9}, {%0,%1,%2,%3};"
        : "+f"(c[0]), "+f"(c[1]), "+f"(c[2]), "+f"(c[3])
        : "r"(a0), "r"(a1), "r"(a2), "r"(a3), "r"(b0), "r"(b1));
}

__device__ __forceinline__ float silu(float x) {
    return x / (1.0f + __expf(-x));
}

// ---------------------------------------------------------------------------
// Pure-bf16 GEMM on pre-split operands, cp.async 4-stage pipeline (dyn smem).
// A: [M][K/2] uint2 (hi|lo bf16x2 pairs), B: [K/2][N] uint2.
// EPI=0: C=..., EPI=1: C+=..., EPI=2: fused swiglu (interleaved w1/w3 cols)
// writing split pairs to OH[row][N/4].
// B0 for blockIdx.y==0 (summary block), else B1.
// Block 128x64, BK=16, 256 threads, warp tile 32x32.
// ---------------------------------------------------------------------------
#define AP 10
#define BP 68
#define NSTG 4
#define GSMEM ((NSTG*128*AP + NSTG*8*BP) * (int)sizeof(uint2))   // 58368 B

template<int EPI>
__global__ void __launch_bounds__(256, 2)
gemm2(const uint2* __restrict__ A, const uint2* __restrict__ B0,
      const uint2* __restrict__ B1, float* __restrict__ C,
      uint2* __restrict__ OH, int M, int N, int K) {
    extern __shared__ __align__(16) uint2 dyn[];
    uint2 (*As)[128][AP] = (uint2(*)[128][AP])dyn;
    uint2 (*Bs)[8][BP]   = (uint2(*)[8][BP])(dyn + NSTG*128*AP);

    const uint2* B = (blockIdx.y == 0) ? B0 : B1;
    int KP = K >> 1;
    int tid = threadIdx.x;
    int m0 = blockIdx.y * 128, n0 = blockIdx.x * 64;
    int wid = tid >> 5, lane = tid & 31;
    int wm = (wid >> 1) * 32, wn = (wid & 1) * 32;
    int g = lane >> 2, tig = lane & 3;

    int ar0 = (tid*2)   >> 2, as0 = (tid*2)   & 3;
    int ar1 = (tid*2+1) >> 2, as1 = (tid*2+1) & 3;
    int br  = tid >> 5, bsg = tid & 31;

    auto issue = [&](int st, int ch) {
        {
            unsigned d = (unsigned)__cvta_generic_to_shared(&As[st][ar0][as0*2]);
            const uint2* s = A + (size_t)(m0 + ar0) * KP + ch*8 + as0*2;
            asm volatile("cp.async.cg.shared.global [%0], [%1], 16;\n" :: "r"(d), "l"(s));
        }
        {
            unsigned d = (unsigned)__cvta_generic_to_shared(&As[st][ar1][as1*2]);
            const uint2* s = A + (size_t)(m0 + ar1) * KP + ch*8 + as1*2;
            asm volatile("cp.async.cg.shared.global [%0], [%1], 16;\n" :: "r"(d), "l"(s));
        }
        {
            unsigned d = (unsigned)__cvta_generic_to_shared(&Bs[st][br][bsg*2]);
            const uint2* s = B + (size_t)(ch*8 + br) * N + n0 + bsg*2;
            asm volatile("cp.async.cg.shared.global [%0], [%1], 16;\n" :: "r"(d), "l"(s));
        }
        asm volatile("cp.async.commit_group;\n" ::);
    };

    int nch = K / 16;
    issue(0, 0);
    issue(1, 1);
    issue(2, 2);

    float c[2][4][4] = {};

    for (int ch = 0; ch < nch; ch++) {
        int st = ch & (NSTG - 1);
        int rem = nch - 1 - ch;
        if (rem >= 2)      asm volatile("cp.async.wait_group 2;\n" ::: "memory");
        else if (rem == 1) asm volatile("cp.async.wait_group 1;\n" ::: "memory");
        else               asm volatile("cp.async.wait_group 0;\n" ::: "memory");
        __syncthreads();
        if (ch + 3 < nch) issue((ch + 3) & (NSTG - 1), ch + 3);

        uint2 af[2][4];
        #pragma unroll
        for (int mt = 0; mt < 2; mt++) {
            int mr = wm + mt * 16 + g;
            af[mt][0] = As[st][mr    ][tig];
            af[mt][1] = As[st][mr + 8][tig];
            af[mt][2] = As[st][mr    ][tig + 4];
            af[mt][3] = As[st][mr + 8][tig + 4];
        }
        uint2 bf[4][2];
        #pragma unroll
        for (int nt = 0; nt < 4; nt++) {
            int nc = wn + nt * 8 + g;
            bf[nt][0] = Bs[st][tig    ][nc];
            bf[nt][1] = Bs[st][tig + 4][nc];
        }
        #pragma unroll
        for (int mt = 0; mt < 2; mt++)
            #pragma unroll
            for (int nt = 0; nt < 4; nt++) {
                mma_bf16(c[mt][nt], af[mt][0].x, af[mt][1].x, af[mt][2].x, af[mt][3].x,
                         bf[nt][0].x, bf[nt][1].x);
                mma_bf16(c[mt][nt], af[mt][0].x, af[mt][1].x, af[mt][2].x, af[mt][3].x,
                         bf[nt][0].y, bf[nt][1].y);
                mma_bf16(c[mt][nt], af[mt][0].y, af[mt][1].y, af[mt][2].y, af[mt][3].y,
                         bf[nt][0].x, bf[nt][1].x);
            }
    }

    #pragma unroll
    for (int mt = 0; mt < 2; mt++) {
        #pragma unroll
        for (int r = 0; r < 2; r++) {
            int row = m0 + wm + mt * 16 + g + r * 8;
            #pragma unroll
            for (int nt = 0; nt < 4; nt++) {
                float v0 = c[mt][nt][r*2+0], v1 = c[mt][nt][r*2+1];
                if (EPI == 2) {
                    // interleaved cols: v0=w1 out, v1=w3 out for h index
                    // hidx = (n0+wn+nt*8)/2 + tig; pair q = (n0+wn+nt*8)/4 + tig/2
                    float hv = silu(v0) * v1;
                    float pv = __shfl_xor_sync(0xffffffffu, hv, 1);
                    if ((tig & 1) == 0) {
                        int q = (n0 + wn + nt * 8) / 4 + (tig >> 1);
                        OH[(size_t)row * (N >> 2) + q] = split_pack(hv, pv);
                    }
                } else {
                    int col = n0 + wn + nt * 8 + tig * 2;
                    float2* cp = (float2*)(C + (size_t)row * N + col);
                    if (EPI == 1) { float2 o = *cp; o.x += v0; o.y += v1; *cp = o; }
                    else          { float2 o; o.x = v0; o.y = v1; *cp = o; }
                }
            }
        }
    }
}

// ---------------------------------------------------------------------------
// Row-based weight pre-split: one block per (l,kp) output row.
// src fp32 [L][K][N] -> dst uint2 [L][K/2][DN] at column coff + nStride*n.
// ---------------------------------------------------------------------------
__global__ void pack_w_rows(const float* __restrict__ src, uint2* __restrict__ dst,
                            int K, int N, int DN, int coff, int nStride) {
    int rowid = blockIdx.x;           // l*(K/2) + kp
    int KP = K >> 1;
    int kp = rowid % KP, l = rowid / KP;
    const float* s0 = src + ((long)l*K + 2*kp) * N;
    const float* s1 = s0 + N;
    uint2* d = dst + (long)rowid * DN + coff;
    for (int n = threadIdx.x; n < N; n += blockDim.x)
        d[(long)n * nStride] = split_pack(s0[n], s1[n]);
}

// tok_emb [V][D] -> [D/2][V] pair layout (for logits B)
__global__ void pack_tok(const float* __restrict__ tok, uint2* __restrict__ dst) {
    int kp = blockIdx.x;              // 0..DP-1
    for (int v = threadIdx.x; v < VV; v += blockDim.x)
        dst[kp * VV + v] = split_pack(tok[(size_t)v*DD + 2*kp],
                                      tok[(size_t)v*DD + 2*kp + 1]);
}

// ---------------------------------------------------------------------------
// Embedding init into the combined residual buffer
// ---------------------------------------------------------------------------
__global__ void embed_kernel(const int* __restrict__ tok,
                             const int* __restrict__ inst,
                             const float* __restrict__ tok_emb,
                             const float* __restrict__ inst_emb,
                             float* __restrict__ xall) {
    int row = blockIdx.x;
    int t = tok[row];
    int ii = inst[row]; ii = ii < 0 ? 0 : (ii > 129 ? 129 : ii);
    const float4* te = (const float4*)(tok_emb  + (size_t)t  * DD);
    const float4* ie = (const float4*)(inst_emb + (size_t)ii * DD);
    float4* xo = (float4*)(xall + (size_t)(SRR + row) * DD);
    for (int d = threadIdx.x; d < DD/4; d += blockDim.x) {
        float4 a = te[d], b = ie[d];
        xo[d] = make_float4(a.x+b.x, a.y+b.y, a.z+b.z, a.w+b.w);
    }
}

__global__ void sum_init_kernel(const float* __restrict__ bar_emb,
                                float* __restrict__ xall) {
    int row = blockIdx.x;
    int bar = row % NBAR;
    const float4* be = (const float4*)(bar_emb + (size_t)bar * DD);
    float4* so = (float4*)(xall + (size_t)row * DD);
    for (int d = threadIdx.x; d < DD/4; d += blockDim.x) so[d] = be[d];
}

// ---------------------------------------------------------------------------
// LayerNorm over combined rows; per-row param select; emits split form.
// ---------------------------------------------------------------------------
__global__ void __launch_bounds__(256)
ln_split(const float* __restrict__ in,
         const float* __restrict__ gS, const float* __restrict__ bS,
         const float* __restrict__ gR, const float* __restrict__ bR,
         uint2* __restrict__ out) {
    int row = blockIdx.x;
    int tid = threadIdx.x;
    const float* gg = (row < SRR) ? gS : gR;
    const float* bb = (row < SRR) ? bS : bR;
    const float2* xr = (const float2*)(in + (size_t)row * DD);
    float2 v = xr[tid];
    __shared__ float sh[256];
    sh[tid] = v.x + v.y; __syncthreads();
    for (int o = 128; o > 0; o >>= 1) { if (tid < o) sh[tid] += sh[tid+o]; __syncthreads(); }
    float mean = sh[0] * (1.0f/DD);
    __syncthreads();
    float d0 = v.x - mean, d1 = v.y - mean;
    sh[tid] = d0*d0 + d1*d1; __syncthreads();
    for (int o = 128; o > 0; o >>= 1) { if (tid < o) sh[tid] += sh[tid+o]; __syncthreads(); }
    float r = rsqrtf(sh[0] * (1.0f/DD) + 1e-5f);
    float y0 = d0 * r * gg[2*tid]   + bb[2*tid];
    float y1 = d1 * r * gg[2*tid+1] + bb[2*tid+1];
    out[(size_t)row * DP + tid] = split_pack(y0, y1);
}

// ---------------------------------------------------------------------------
// RoPE over combined QKV buffer (heads 0..15 = Q+K); V untouched.
// ---------------------------------------------------------------------------
__global__ void rope2(float* __restrict__ buf) {
    const float LOGF = 9.210340371976184f / 32.0f;
    int total = MALL * 16 * 32;
    for (int idx = blockIdx.x * blockDim.x + threadIdx.x; idx < total;
         idx += gridDim.x * blockDim.x) {
        int row  = idx >> 9;
        int rem  = idx & 511;
        int head = rem >> 5;
        int d    = rem & 31;
        int pos  = (row < SRR) ? (row & (NBAR-1)) : ((row - SRR) & (SS-1));
        float inv = __expf(-(float)d * LOGF);
        float f = (float)pos * inv;
        float c, s; __sincosf(f, &s, &c);
        float* p = buf + (size_t)row * QKVLD + head * 64;
        float x1 = p[d], x2 = p[d + 32];
        p[d]      = x1 * c - x2 * s;
        p[d + 32] = x1 * s + x2 * c;
    }
}

// ---------------------------------------------------------------------------
// Merged-head range-sparse attention: one block (256 thr = 8 warps) per qrow;
// warp w handles head w. Emits split output.
// ---------------------------------------------------------------------------
__global__ void __launch_bounds__(256)
attn3(const float* __restrict__ qkv, const int* __restrict__ chord,
      uint2* __restrict__ O) {
    int qrow = blockIdx.x;
    int tid  = threadIdx.x;
    int wid  = tid >> 5;
    int lane = tid & 31;
    bool sum = qrow < SRR;
    int b, qi;
    if (sum) { b = qrow / NBAR; qi = qrow % NBAR; }
    else     { int r = qrow - SRR; b = r / SS; qi = r % SS; }
    const int* ch = chord + b * SS;

    __shared__ float sc[HH][KTOT];
    __shared__ float ored[HH][DHH];
    __shared__ int   sN1, sN2, sTs;

    if (tid == 0) {
        int target = sum ? qi : ch[qi];
        int lo = 0, hi = SS;
        while (lo < hi) { int mid = (lo + hi) >> 1; if (ch[mid] < target) lo = mid + 1; else hi = mid; }
        int tstart = lo;
        int n1, n2;
        if (sum) {
            int lo2 = tstart, hi2 = SS;
            while (lo2 < hi2) { int mid = (lo2 + hi2) >> 1; if (ch[mid] < target + 1) lo2 = mid + 1; else hi2 = mid; }
            n1 = qi + 1;
            n2 = lo2 - tstart;
        } else {
            n1 = target;
            n2 = qi - tstart + 1;
        }
        sN1 = n1; sN2 = n2; sTs = tstart;
    }
    __syncthreads();
    int n1 = sN1, n2 = sN2, ts = sTs;
    int n = n1 + n2;

    // q for this head into per-warp smem
    const float* qp = qkv + (size_t)qrow * QKVLD + wid * DHH;
    ored[wid][lane]      = qp[lane];
    ored[wid][lane + 32] = qp[lane + 32];
    __syncwarp();

    // scores: lanes stride keys
    const float4* q4 = (const float4*)ored[wid];
    for (int j = lane; j < n; j += 32) {
        int krow = (j < n1) ? (b * NBAR + j) : (SRR + b * SS + ts + (j - n1));
        const float4* k4 = (const float4*)(qkv + (size_t)krow * QKVLD + 512 + wid * DHH);
        float acc = 0.0f;
        #pragma unroll
        for (int d = 0; d < DHH/4; d++) {
            float4 a = q4[d], kk = k4[d];
            acc += a.x*kk.x + a.y*kk.y + a.z*kk.z + a.w*kk.w;
        }
        sc[wid][j] = acc * 0.125f;
    }
    __syncwarp();

    // warp softmax
    float mx = -1e30f;
    for (int j = lane; j < n; j += 32) mx = fmaxf(mx, sc[wid][j]);
    #pragma unroll
    for (int o = 16; o > 0; o >>= 1) mx = fmaxf(mx, __shfl_xor_sync(0xffffffffu, mx, o));
    float sm = 0.0f;
    for (int j = lane; j < n; j += 32) {
        float e = __expf(sc[wid][j] - mx);
        sc[wid][j] = e;
        sm += e;
    }
    #pragma unroll
    for (int o = 16; o > 0; o >>= 1) sm += __shfl_xor_sync(0xffffffffu, sm, o);
    float invs = 1.0f / sm;
    __syncwarp();

    // V accumulation: lane owns dims lane, lane+32
    float a0 = 0.0f, a1 = 0.0f;
    for (int j = 0; j < n; j++) {
        int vrow = (j < n1) ? (b * NBAR + j) : (SRR + b * SS + ts + (j - n1));
        const float* vv = qkv + (size_t)vrow * QKVLD + 1024 + wid * DHH;
        float s = sc[wid][j];
        a0 += s * vv[lane];
        a1 += s * vv[lane + 32];
    }
    ored[wid][lane]      = a0 * invs;
    ored[wid][lane + 32] = a1 * invs;
    __syncwarp();

    O[(size_t)qrow * DP + wid * 32 + lane] =
        split_pack(ored[wid][2*lane], ored[wid][2*lane + 1]);
}

// ---------------------------------------------------------------------------
// Host side
// ---------------------------------------------------------------------------
static float* devptrf(const void* sym) {
    void* p = nullptr; cudaGetSymbolAddress(&p, sym); return (float*)p;
}
static uint2* devptru(const void* sym) {
    void* p = nullptr; cudaGetSymbolAddress(&p, sym); return (uint2*)p;
}

extern "C" void kernel_launch(void* const* d_in, const int* in_sizes, int n_in,
                              void* d_out, int out_size) {
    const int* tok   = (const int*)d_in[0];
    const int* chord = (const int*)d_in[1];
    const int* inst  = (const int*)d_in[2];
    int o = (in_sizes[3] == 1) ? 4 : 3;
    const float* tok_emb  = (const float*)d_in[o + 0];
    const float* inst_emb = (const float*)d_in[o + 1];
    const float* bar_emb  = (const float*)d_in[o + 2];
    const float* ln_as_g  = (const float*)d_in[o + 3];
    const float* ln_as_b  = (const float*)d_in[o + 4];
    const float* ln_ar_g  = (const float*)d_in[o + 5];
    const float* ln_ar_b  = (const float*)d_in[o + 6];
    const float* ln_fs_g  = (const float*)d_in[o + 7];
    const float* ln_fs_b  = (const float*)d_in[o + 8];
    const float* ln_fr_g  = (const float*)d_in[o + 9];
    const float* ln_fr_b  = (const float*)d_in[o + 10];
    const float* Wq       = (const float*)d_in[o + 11];
    const float* Wk       = (const float*)d_in[o + 12];
    const float* Wv       = (const float*)d_in[o + 13];
    const float* Wo       = (const float*)d_in[o + 14];
    const float* fs_w1    = (const float*)d_in[o + 15];
    const float* fs_w3    = (const float*)d_in[o + 16];
    const float* fs_w2    = (const float*)d_in[o + 17];
    const float* fr_w1    = (const float*)d_in[o + 18];
    const float* fr_w3    = (const float*)d_in[o + 19];
    const float* fr_w2    = (const float*)d_in[o + 20];
    const float* out_g    = (const float*)d_in[o + 21];
    const float* out_b    = (const float*)d_in[o + 22];
    float* out = (float*)d_out;

    float* xall = devptrf(g_xall);
    uint2* lnb  = devptru(g_ln);
    float* qkv  = devptrf(g_qkv);
    uint2* Ob   = devptru(g_Os);
    uint2* hs   = devptru(g_hs);
    uint2* wqkv = devptru(g_wqkv);
    uint2* wo   = devptru(g_wo);
    uint2* w13s = devptru(g_w13s);
    uint2* w13r = devptru(g_w13r);
    uint2* w2s  = devptru(g_w2s);
    uint2* w2r  = devptru(g_w2r);
    uint2* tokT = devptru(g_tokT);

    cudaFuncSetAttribute(gemm2<0>, cudaFuncAttributeMaxDynamicSharedMemorySize, GSMEM);
    cudaFuncSetAttribute(gemm2<1>, cudaFuncAttributeMaxDynamicSharedMemorySize, GSMEM);
    cudaFuncSetAttribute(gemm2<2>, cudaFuncAttributeMaxDynamicSharedMemorySize, GSMEM);

    // ---- weight pre-split (row-based). w13: interleave w1->2n, w3->2n+1 ----
    pack_w_rows<<<LL*DP, 256>>>(Wq, wqkv, DD, DD, 1536, 0, 1);
    pack_w_rows<<<LL*DP, 256>>>(Wk, wqkv, DD, DD, 1536, 512, 1);
    pack_w_rows<<<LL*DP, 256>>>(Wv, wqkv, DD, DD, 1536, 1024, 1);
    pack_w_rows<<<LL*DP, 256>>>(Wo, wo, DD, DD, DD, 0, 1);
    pack_w_rows<<<LL*DP, 256>>>(fs_w1, w13s, DD, FF, 2*FF, 0, 2);
    pack_w_rows<<<LL*DP, 256>>>(fs_w3, w13s, DD, FF, 2*FF, 1, 2);
    pack_w_rows<<<LL*DP, 256>>>(fr_w1, w13r, DD, FF, 2*FF, 0, 2);
    pack_w_rows<<<LL*DP, 256>>>(fr_w3, w13r, DD, FF, 2*FF, 1, 2);
    pack_w_rows<<<LL*FP, 256>>>(fs_w2, w2s, FF, DD, DD, 0, 1);
    pack_w_rows<<<LL*FP, 256>>>(fr_w2, w2r, FF, DD, DD, 0, 1);
    pack_tok<<<DP, 256>>>(tok_emb, tokT);

    // ---- embeddings ----
    embed_kernel<<<RR, 128>>>(tok, inst, tok_emb, inst_emb, xall);
    sum_init_kernel<<<SRR, 128>>>(bar_emb, xall);

    for (int l = 0; l < LL; l++) {
        uint2* wqkv_l = wqkv + (size_t)l * DP * 1536;
        uint2* wo_l   = wo   + (size_t)l * DP * DD;
        uint2* w13s_l = w13s + (size_t)l * DP * 2*FF;
        uint2* w13r_l = w13r + (size_t)l * DP * 2*FF;
        uint2* w2s_l  = w2s  + (size_t)l * FP * DD;
        uint2* w2r_l  = w2r  + (size_t)l * FP * DD;

        // --- attention ---
        ln_split<<<MALL, 256>>>(xall, ln_as_g + l*DD, ln_as_b + l*DD,
                                ln_ar_g + l*DD, ln_ar_b + l*DD, lnb);
        gemm2<0><<<dim3(1536/64, MALL/128), 256, GSMEM>>>(
            lnb, wqkv_l, wqkv_l, qkv, nullptr, MALL, 1536, DD);
        rope2<<<2048, 256>>>(qkv);
        attn3<<<MALL, 256>>>(qkv, chord, Ob);
        gemm2<1><<<dim3(DD/64, MALL/128), 256, GSMEM>>>(
            Ob, wo_l, wo_l, xall, nullptr, MALL, DD, DD);

        // --- FFN (w13 fused swiglu epilogue) ---
        ln_split<<<MALL, 256>>>(xall, ln_fs_g + l*DD, ln_fs_b + l*DD,
                                ln_fr_g + l*DD, ln_fr_b + l*DD, lnb);
        gemm2<2><<<dim3((2*FF)/64, MALL/128), 256, GSMEM>>>(
            lnb, w13s_l, w13r_l, nullptr, hs, MALL, 2*FF, DD);
        gemm2<1><<<dim3(DD/64, MALL/128), 256, GSMEM>>>(
            hs, w2s_l, w2r_l, xall, nullptr, MALL, DD, FF);
    }

    // final LN + logits on regular rows
    ln_split<<<MALL, 256>>>(xall, out_g, out_b, out_g, out_b, lnb);
    gemm2<0><<<dim3(VV/64, RR/128), 256, GSMEM>>>(
        lnb + (size_t)SRR * DP, tokT, tokT, out, nullptr, RR, VV, DD);
}

// round 16
// speedup vs baseline: 2.5687x; 1.0175x over previous
#include <cuda_runtime.h>
#include <cuda_bf16.h>
#include <math.h>

// ---------------------------------------------------------------------------
// Problem constants
// ---------------------------------------------------------------------------
#define BB   2
#define SS   1024
#define NBAR 64
#define DD   512
#define HH   8
#define DHH  64
#define FF   2048
#define LL   12
#define VV   1024

#define RR   (BB*SS)        // 2048
#define SRR  (BB*NBAR)      // 128
#define MALL (SRR+RR)       // 2176 = 17*128  (summary rows first)
#define DP   (DD/2)         // 256 k-pairs
#define FP   (FF/2)         // 1024 k-pairs
#define QKVLD 1536
#define KTOT (NBAR+SS)      // 1088

// ---------------------------------------------------------------------------
// Device scratch
// ---------------------------------------------------------------------------
__device__ float g_xall[MALL*DD];
__device__ __align__(16) uint2 g_ln  [MALL*DP];
__device__ float g_qkv [MALL*QKVLD];
__device__ __align__(16) uint2 g_Os  [MALL*DP];
__device__ __align__(16) uint2 g_hs  [MALL*FP];
__device__ __align__(16) uint2 g_wqkv[LL*DP*1536];
__device__ __align__(16) uint2 g_wo  [LL*DP*DD];
__device__ __align__(16) uint2 g_w13s[LL*DP*2*FF];
__device__ __align__(16) uint2 g_w13r[LL*DP*2*FF];
__device__ __align__(16) uint2 g_w2s [LL*FP*DD];
__device__ __align__(16) uint2 g_w2r [LL*FP*DD];
__device__ __align__(16) uint2 g_tokT[DP*VV];

// ---------------------------------------------------------------------------
// bf16 split helpers
// ---------------------------------------------------------------------------
__device__ __forceinline__ uint2 split_pack(float x0, float x1) {
    __nv_bfloat16 h0 = __float2bfloat16(x0);
    __nv_bfloat16 h1 = __float2bfloat16(x1);
    float r0 = x0 - __bfloat162float(h0);
    float r1 = x1 - __bfloat162float(h1);
    __nv_bfloat16 l0 = __float2bfloat16(r0);
    __nv_bfloat16 l1 = __float2bfloat16(r1);
    uint2 t;
    t.x = ((unsigned)__bfloat16_as_ushort(h1) << 16) | __bfloat16_as_ushort(h0);
    t.y = ((unsigned)__bfloat16_as_ushort(l1) << 16) | __bfloat16_as_ushort(l0);
    return t;
}

__device__ __forceinline__ void mma_bf16(float c[4],
                                         unsigned a0, unsigned a1, unsigned a2, unsigned a3,
                                         unsigned b0, unsigned b1) {
    asm volatile(
        "mma.sync.aligned.m16n8k16.row.col.f32.bf16.bf16.f32 "
        "{%0,%1,%2,%3}, {%4,%5,%6,%7}, {%8,%9}, {%0,%1,%2,%3};"
        : "+f"(c[0]), "+f"(c[1]), "+f"(c[2]), "+f"(c[3])
        : "r"(a0), "r"(a1), "r"(a2), "r"(a3), "r"(b0), "r"(b1));
}

__device__ __forceinline__ float silu(float x) {
    return x / (1.0f + __expf(-x));
}

// ---------------------------------------------------------------------------
// BM=128 bf16 GEMM (256 thr, 8 warps 32x32), cp.async 4-stage.
// EPI=0: C=, EPI=1: C+=, EPI=2: fused swiglu -> OH split pairs.
// B0 for blockIdx.y==0, else B1.
// ---------------------------------------------------------------------------
#define AP 10
#define BP 68
#define NSTG 4
#define GSMEM ((NSTG*128*AP + NSTG*8*BP) * (int)sizeof(uint2))   // 58368 B

template<int EPI>
__global__ void __launch_bounds__(256, 2)
gemm2(const uint2* __restrict__ A, const uint2* __restrict__ B0,
      const uint2* __restrict__ B1, float* __restrict__ C,
      uint2* __restrict__ OH, int M, int N, int K) {
    extern __shared__ __align__(16) uint2 dyn[];
    uint2 (*As)[128][AP] = (uint2(*)[128][AP])dyn;
    uint2 (*Bs)[8][BP]   = (uint2(*)[8][BP])(dyn + NSTG*128*AP);

    const uint2* B = (blockIdx.y == 0) ? B0 : B1;
    int KP = K >> 1;
    int tid = threadIdx.x;
    int m0 = blockIdx.y * 128, n0 = blockIdx.x * 64;
    int wid = tid >> 5, lane = tid & 31;
    int wm = (wid >> 1) * 32, wn = (wid & 1) * 32;
    int g = lane >> 2, tig = lane & 3;

    int ar0 = (tid*2)   >> 2, as0 = (tid*2)   & 3;
    int ar1 = (tid*2+1) >> 2, as1 = (tid*2+1) & 3;
    int br  = tid >> 5, bsg = tid & 31;

    auto issue = [&](int st, int ch) {
        {
            unsigned d = (unsigned)__cvta_generic_to_shared(&As[st][ar0][as0*2]);
            const uint2* s = A + (size_t)(m0 + ar0) * KP + ch*8 + as0*2;
            asm volatile("cp.async.cg.shared.global [%0], [%1], 16;\n" :: "r"(d), "l"(s));
        }
        {
            unsigned d = (unsigned)__cvta_generic_to_shared(&As[st][ar1][as1*2]);
            const uint2* s = A + (size_t)(m0 + ar1) * KP + ch*8 + as1*2;
            asm volatile("cp.async.cg.shared.global [%0], [%1], 16;\n" :: "r"(d), "l"(s));
        }
        {
            unsigned d = (unsigned)__cvta_generic_to_shared(&Bs[st][br][bsg*2]);
            const uint2* s = B + (size_t)(ch*8 + br) * N + n0 + bsg*2;
            asm volatile("cp.async.cg.shared.global [%0], [%1], 16;\n" :: "r"(d), "l"(s));
        }
        asm volatile("cp.async.commit_group;\n" ::);
    };

    int nch = K / 16;
    issue(0, 0);
    issue(1, 1);
    issue(2, 2);

    float c[2][4][4] = {};

    for (int ch = 0; ch < nch; ch++) {
        int st = ch & (NSTG - 1);
        int rem = nch - 1 - ch;
        if (rem >= 2)      asm volatile("cp.async.wait_group 2;\n" ::: "memory");
        else if (rem == 1) asm volatile("cp.async.wait_group 1;\n" ::: "memory");
        else               asm volatile("cp.async.wait_group 0;\n" ::: "memory");
        __syncthreads();
        if (ch + 3 < nch) issue((ch + 3) & (NSTG - 1), ch + 3);

        uint2 af[2][4];
        #pragma unroll
        for (int mt = 0; mt < 2; mt++) {
            int mr = wm + mt * 16 + g;
            af[mt][0] = As[st][mr    ][tig];
            af[mt][1] = As[st][mr + 8][tig];
            af[mt][2] = As[st][mr    ][tig + 4];
            af[mt][3] = As[st][mr + 8][tig + 4];
        }
        uint2 bf[4][2];
        #pragma unroll
        for (int nt = 0; nt < 4; nt++) {
            int nc = wn + nt * 8 + g;
            bf[nt][0] = Bs[st][tig    ][nc];
            bf[nt][1] = Bs[st][tig + 4][nc];
        }
        #pragma unroll
        for (int mt = 0; mt < 2; mt++)
            #pragma unroll
            for (int nt = 0; nt < 4; nt++) {
                mma_bf16(c[mt][nt], af[mt][0].x, af[mt][1].x, af[mt][2].x, af[mt][3].x,
                         bf[nt][0].x, bf[nt][1].x);
                mma_bf16(c[mt][nt], af[mt][0].x, af[mt][1].x, af[mt][2].x, af[mt][3].x,
                         bf[nt][0].y, bf[nt][1].y);
                mma_bf16(c[mt][nt], af[mt][0].y, af[mt][1].y, af[mt][2].y, af[mt][3].y,
                         bf[nt][0].x, bf[nt][1].x);
            }
    }

    #pragma unroll
    for (int mt = 0; mt < 2; mt++) {
        #pragma unroll
        for (int r = 0; r < 2; r++) {
            int row = m0 + wm + mt * 16 + g + r * 8;
            #pragma unroll
            for (int nt = 0; nt < 4; nt++) {
                float v0 = c[mt][nt][r*2+0], v1 = c[mt][nt][r*2+1];
                if (EPI == 2) {
                    float hv = silu(v0) * v1;
                    float pv = __shfl_xor_sync(0xffffffffu, hv, 1);
                    if ((tig & 1) == 0) {
                        int q = (n0 + wn + nt * 8) / 4 + (tig >> 1);
                        OH[(size_t)row * (N >> 2) + q] = split_pack(hv, pv);
                    }
                } else {
                    int col = n0 + wn + nt * 8 + tig * 2;
                    float2* cp = (float2*)(C + (size_t)row * N + col);
                    if (EPI == 1) { float2 o = *cp; o.x += v0; o.y += v1; *cp = o; }
                    else          { float2 o; o.x = v0; o.y = v1; *cp = o; }
                }
            }
        }
    }
}

// ---------------------------------------------------------------------------
// BM=64 bf16 GEMM (128 thr, 4 warps 32x32), cp.async 4-stage, ACC epilogue.
// For narrow-N GEMMs (WO, W2): grid (N/64, M/64) = 272 CTAs -> full chip.
// B0 for blockIdx.y < ySplit (summary rows, 2 blocks at BM=64), else B1.
// ---------------------------------------------------------------------------
#define GSMEM64 ((NSTG*64*AP + NSTG*8*BP) * (int)sizeof(uint2))   // 37888 B

__global__ void __launch_bounds__(128, 4)
gemm64(const uint2* __restrict__ A, const uint2* __restrict__ B0,
       const uint2* __restrict__ B1, float* __restrict__ C,
       int M, int N, int K, int ySplit) {
    extern __shared__ __align__(16) uint2 dyn[];
    uint2 (*As)[64][AP] = (uint2(*)[64][AP])dyn;
    uint2 (*Bs)[8][BP]  = (uint2(*)[8][BP])(dyn + NSTG*64*AP);

    const uint2* B = ((int)blockIdx.y < ySplit) ? B0 : B1;
    int KP = K >> 1;
    int tid = threadIdx.x;
    int m0 = blockIdx.y * 64, n0 = blockIdx.x * 64;
    int wid = tid >> 5, lane = tid & 31;
    int wm = (wid >> 1) * 32, wn = (wid & 1) * 32;
    int g = lane >> 2, tig = lane & 3;

    // A loader: 2 x 16B; transfers 0..255 cover 64 rows x 4 segs
    int ar0 = (tid*2)   >> 2, as0 = (tid*2)   & 3;
    int ar1 = (tid*2+1) >> 2, as1 = (tid*2+1) & 3;
    // B loader: 2 x 16B; row tid>>4 (0..7), segs (tid&15) and (tid&15)+16
    int br = tid >> 4, bs0 = tid & 15, bs1 = (tid & 15) + 16;

    auto issue = [&](int st, int ch) {
        {
            unsigned d = (unsigned)__cvta_generic_to_shared(&As[st][ar0][as0*2]);
            const uint2* s = A + (size_t)(m0 + ar0) * KP + ch*8 + as0*2;
            asm volatile("cp.async.cg.shared.global [%0], [%1], 16;\n" :: "r"(d), "l"(s));
        }
        {
            unsigned d = (unsigned)__cvta_generic_to_shared(&As[st][ar1][as1*2]);
            const uint2* s = A + (size_t)(m0 + ar1) * KP + ch*8 + as1*2;
            asm volatile("cp.async.cg.shared.global [%0], [%1], 16;\n" :: "r"(d), "l"(s));
        }
        {
            unsigned d = (unsigned)__cvta_generic_to_shared(&Bs[st][br][bs0*2]);
            const uint2* s = B + (size_t)(ch*8 + br) * N + n0 + bs0*2;
            asm volatile("cp.async.cg.shared.global [%0], [%1], 16;\n" :: "r"(d), "l"(s));
        }
        {
            unsigned d = (unsigned)__cvta_generic_to_shared(&Bs[st][br][bs1*2]);
            const uint2* s = B + (size_t)(ch*8 + br) * N + n0 + bs1*2;
            asm volatile("cp.async.cg.shared.global [%0], [%1], 16;\n" :: "r"(d), "l"(s));
        }
        asm volatile("cp.async.commit_group;\n" ::);
    };

    int nch = K / 16;
    issue(0, 0);
    issue(1, 1);
    issue(2, 2);

    float c[2][4][4] = {};

    for (int ch = 0; ch < nch; ch++) {
        int st = ch & (NSTG - 1);
        int rem = nch - 1 - ch;
        if (rem >= 2)      asm volatile("cp.async.wait_group 2;\n" ::: "memory");
        else if (rem == 1) asm volatile("cp.async.wait_group 1;\n" ::: "memory");
        else               asm volatile("cp.async.wait_group 0;\n" ::: "memory");
        __syncthreads();
        if (ch + 3 < nch) issue((ch + 3) & (NSTG - 1), ch + 3);

        uint2 af[2][4];
        #pragma unroll
        for (int mt = 0; mt < 2; mt++) {
            int mr = wm + mt * 16 + g;
            af[mt][0] = As[st][mr    ][tig];
            af[mt][1] = As[st][mr + 8][tig];
            af[mt][2] = As[st][mr    ][tig + 4];
            af[mt][3] = As[st][mr + 8][tig + 4];
        }
        uint2 bf[4][2];
        #pragma unroll
        for (int nt = 0; nt < 4; nt++) {
            int nc = wn + nt * 8 + g;
            bf[nt][0] = Bs[st][tig    ][nc];
            bf[nt][1] = Bs[st][tig + 4][nc];
        }
        #pragma unroll
        for (int mt = 0; mt < 2; mt++)
            #pragma unroll
            for (int nt = 0; nt < 4; nt++) {
                mma_bf16(c[mt][nt], af[mt][0].x, af[mt][1].x, af[mt][2].x, af[mt][3].x,
                         bf[nt][0].x, bf[nt][1].x);
                mma_bf16(c[mt][nt], af[mt][0].x, af[mt][1].x, af[mt][2].x, af[mt][3].x,
                         bf[nt][0].y, bf[nt][1].y);
                mma_bf16(c[mt][nt], af[mt][0].y, af[mt][1].y, af[mt][2].y, af[mt][3].y,
                         bf[nt][0].x, bf[nt][1].x);
            }
    }

    #pragma unroll
    for (int mt = 0; mt < 2; mt++) {
        #pragma unroll
        for (int r = 0; r < 2; r++) {
            int row = m0 + wm + mt * 16 + g + r * 8;
            #pragma unroll
            for (int nt = 0; nt < 4; nt++) {
                int col = n0 + wn + nt * 8 + tig * 2;
                float2* cp = (float2*)(C + (size_t)row * N + col);
                float2 o = *cp;
                o.x += c[mt][nt][r*2+0];
                o.y += c[mt][nt][r*2+1];
                *cp = o;
            }
        }
    }
}

// ---------------------------------------------------------------------------
// Row-based weight pre-split
// ---------------------------------------------------------------------------
__global__ void pack_w_rows(const float* __restrict__ src, uint2* __restrict__ dst,
                            int K, int N, int DN, int coff, int nStride) {
    int rowid = blockIdx.x;
    int KP = K >> 1;
    int kp = rowid % KP, l = rowid / KP;
    const float* s0 = src + ((long)l*K + 2*kp) * N;
    const float* s1 = s0 + N;
    uint2* d = dst + (long)rowid * DN + coff;
    for (int n = threadIdx.x; n < N; n += blockDim.x)
        d[(long)n * nStride] = split_pack(s0[n], s1[n]);
}

__global__ void pack_tok(const float* __restrict__ tok, uint2* __restrict__ dst) {
    int kp = blockIdx.x;
    for (int v = threadIdx.x; v < VV; v += blockDim.x)
        dst[kp * VV + v] = split_pack(tok[(size_t)v*DD + 2*kp],
                                      tok[(size_t)v*DD + 2*kp + 1]);
}

// ---------------------------------------------------------------------------
// Embedding init
// ---------------------------------------------------------------------------
__global__ void embed_kernel(const int* __restrict__ tok,
                             const int* __restrict__ inst,
                             const float* __restrict__ tok_emb,
                             const float* __restrict__ inst_emb,
                             float* __restrict__ xall) {
    int row = blockIdx.x;
    int t = tok[row];
    int ii = inst[row]; ii = ii < 0 ? 0 : (ii > 129 ? 129 : ii);
    const float4* te = (const float4*)(tok_emb  + (size_t)t  * DD);
    const float4* ie = (const float4*)(inst_emb + (size_t)ii * DD);
    float4* xo = (float4*)(xall + (size_t)(SRR + row) * DD);
    for (int d = threadIdx.x; d < DD/4; d += blockDim.x) {
        float4 a = te[d], b = ie[d];
        xo[d] = make_float4(a.x+b.x, a.y+b.y, a.z+b.z, a.w+b.w);
    }
}

__global__ void sum_init_kernel(const float* __restrict__ bar_emb,
                                float* __restrict__ xall) {
    int row = blockIdx.x;
    int bar = row % NBAR;
    const float4* be = (const float4*)(bar_emb + (size_t)bar * DD);
    float4* so = (float4*)(xall + (size_t)row * DD);
    for (int d = threadIdx.x; d < DD/4; d += blockDim.x) so[d] = be[d];
}

// ---------------------------------------------------------------------------
// LayerNorm (emits split form)
// ---------------------------------------------------------------------------
__global__ void __launch_bounds__(256)
ln_split(const float* __restrict__ in,
         const float* __restrict__ gS, const float* __restrict__ bS,
         const float* __restrict__ gR, const float* __restrict__ bR,
         uint2* __restrict__ out) {
    int row = blockIdx.x;
    int tid = threadIdx.x;
    const float* gg = (row < SRR) ? gS : gR;
    const float* bb = (row < SRR) ? bS : bR;
    const float2* xr = (const float2*)(in + (size_t)row * DD);
    float2 v = xr[tid];
    __shared__ float sh[256];
    sh[tid] = v.x + v.y; __syncthreads();
    for (int o = 128; o > 0; o >>= 1) { if (tid < o) sh[tid] += sh[tid+o]; __syncthreads(); }
    float mean = sh[0] * (1.0f/DD);
    __syncthreads();
    float d0 = v.x - mean, d1 = v.y - mean;
    sh[tid] = d0*d0 + d1*d1; __syncthreads();
    for (int o = 128; o > 0; o >>= 1) { if (tid < o) sh[tid] += sh[tid+o]; __syncthreads(); }
    float r = rsqrtf(sh[0] * (1.0f/DD) + 1e-5f);
    float y0 = d0 * r * gg[2*tid]   + bb[2*tid];
    float y1 = d1 * r * gg[2*tid+1] + bb[2*tid+1];
    out[(size_t)row * DP + tid] = split_pack(y0, y1);
}

// ---------------------------------------------------------------------------
// RoPE over packed QKV (heads 0..15 = Q+K)
// ---------------------------------------------------------------------------
__global__ void rope2(float* __restrict__ buf) {
    const float LOGF = 9.210340371976184f / 32.0f;
    int total = MALL * 16 * 32;
    for (int idx = blockIdx.x * blockDim.x + threadIdx.x; idx < total;
         idx += gridDim.x * blockDim.x) {
        int row  = idx >> 9;
        int rem  = idx & 511;
        int head = rem >> 5;
        int d    = rem & 31;
        int pos  = (row < SRR) ? (row & (NBAR-1)) : ((row - SRR) & (SS-1));
        float inv = __expf(-(float)d * LOGF);
        float f = (float)pos * inv;
        float c, s; __sincosf(f, &s, &c);
        float* p = buf + (size_t)row * QKVLD + head * 64;
        float x1 = p[d], x2 = p[d + 32];
        p[d]      = x1 * c - x2 * s;
        p[d + 32] = x1 * s + x2 * c;
    }
}

// ---------------------------------------------------------------------------
// Merged-head range-sparse attention: 1 block (8 warps) per qrow.
// ---------------------------------------------------------------------------
__global__ void __launch_bounds__(256)
attn3(const float* __restrict__ qkv, const int* __restrict__ chord,
      uint2* __restrict__ O) {
    int qrow = blockIdx.x;
    int tid  = threadIdx.x;
    int wid  = tid >> 5;
    int lane = tid & 31;
    bool sum = qrow < SRR;
    int b, qi;
    if (sum) { b = qrow / NBAR; qi = qrow % NBAR; }
    else     { int r = qrow - SRR; b = r / SS; qi = r % SS; }
    const int* ch = chord + b * SS;

    __shared__ float sc[HH][KTOT];
    __shared__ float ored[HH][DHH];
    __shared__ int   sN1, sN2, sTs;

    if (tid == 0) {
        int target = sum ? qi : ch[qi];
        int lo = 0, hi = SS;
        while (lo < hi) { int mid = (lo + hi) >> 1; if (ch[mid] < target) lo = mid + 1; else hi = mid; }
        int tstart = lo;
        int n1, n2;
        if (sum) {
            int lo2 = tstart, hi2 = SS;
            while (lo2 < hi2) { int mid = (lo2 + hi2) >> 1; if (ch[mid] < target + 1) lo2 = mid + 1; else hi2 = mid; }
            n1 = qi + 1;
            n2 = lo2 - tstart;
        } else {
            n1 = target;
            n2 = qi - tstart + 1;
        }
        sN1 = n1; sN2 = n2; sTs = tstart;
    }
    __syncthreads();
    int n1 = sN1, n2 = sN2, ts = sTs;
    int n = n1 + n2;

    const float* qp = qkv + (size_t)qrow * QKVLD + wid * DHH;
    ored[wid][lane]      = qp[lane];
    ored[wid][lane + 32] = qp[lane + 32];
    __syncwarp();

    const float4* q4 = (const float4*)ored[wid];
    for (int j = lane; j < n; j += 32) {
        int krow = (j < n1) ? (b * NBAR + j) : (SRR + b * SS + ts + (j - n1));
        const float4* k4 = (const float4*)(qkv + (size_t)krow * QKVLD + 512 + wid * DHH);
        float acc = 0.0f;
        #pragma unroll
        for (int d = 0; d < DHH/4; d++) {
            float4 a = q4[d], kk = k4[d];
            acc += a.x*kk.x + a.y*kk.y + a.z*kk.z + a.w*kk.w;
        }
        sc[wid][j] = acc * 0.125f;
    }
    __syncwarp();

    float mx = -1e30f;
    for (int j = lane; j < n; j += 32) mx = fmaxf(mx, sc[wid][j]);
    #pragma unroll
    for (int o = 16; o > 0; o >>= 1) mx = fmaxf(mx, __shfl_xor_sync(0xffffffffu, mx, o));
    float sm = 0.0f;
    for (int j = lane; j < n; j += 32) {
        float e = __expf(sc[wid][j] - mx);
        sc[wid][j] = e;
        sm += e;
    }
    #pragma unroll
    for (int o = 16; o > 0; o >>= 1) sm += __shfl_xor_sync(0xffffffffu, sm, o);
    float invs = 1.0f / sm;
    __syncwarp();

    float a0 = 0.0f, a1 = 0.0f;
    for (int j = 0; j < n; j++) {
        int vrow = (j < n1) ? (b * NBAR + j) : (SRR + b * SS + ts + (j - n1));
        const float* vv = qkv + (size_t)vrow * QKVLD + 1024 + wid * DHH;
        float s = sc[wid][j];
        a0 += s * vv[lane];
        a1 += s * vv[lane + 32];
    }
    ored[wid][lane]      = a0 * invs;
    ored[wid][lane + 32] = a1 * invs;
    __syncwarp();

    O[(size_t)qrow * DP + wid * 32 + lane] =
        split_pack(ored[wid][2*lane], ored[wid][2*lane + 1]);
}

// ---------------------------------------------------------------------------
// Host side
// ---------------------------------------------------------------------------
static float* devptrf(const void* sym) {
    void* p = nullptr; cudaGetSymbolAddress(&p, sym); return (float*)p;
}
static uint2* devptru(const void* sym) {
    void* p = nullptr; cudaGetSymbolAddress(&p, sym); return (uint2*)p;
}

extern "C" void kernel_launch(void* const* d_in, const int* in_sizes, int n_in,
                              void* d_out, int out_size) {
    const int* tok   = (const int*)d_in[0];
    const int* chord = (const int*)d_in[1];
    const int* inst  = (const int*)d_in[2];
    int o = (in_sizes[3] == 1) ? 4 : 3;
    const float* tok_emb  = (const float*)d_in[o + 0];
    const float* inst_emb = (const float*)d_in[o + 1];
    const float* bar_emb  = (const float*)d_in[o + 2];
    const float* ln_as_g  = (const float*)d_in[o + 3];
    const float* ln_as_b  = (const float*)d_in[o + 4];
    const float* ln_ar_g  = (const float*)d_in[o + 5];
    const float* ln_ar_b  = (const float*)d_in[o + 6];
    const float* ln_fs_g  = (const float*)d_in[o + 7];
    const float* ln_fs_b  = (const float*)d_in[o + 8];
    const float* ln_fr_g  = (const float*)d_in[o + 9];
    const float* ln_fr_b  = (const float*)d_in[o + 10];
    const float* Wq       = (const float*)d_in[o + 11];
    const float* Wk       = (const float*)d_in[o + 12];
    const float* Wv       = (const float*)d_in[o + 13];
    const float* Wo       = (const float*)d_in[o + 14];
    const float* fs_w1    = (const float*)d_in[o + 15];
    const float* fs_w3    = (const float*)d_in[o + 16];
    const float* fs_w2    = (const float*)d_in[o + 17];
    const float* fr_w1    = (const float*)d_in[o + 18];
    const float* fr_w3    = (const float*)d_in[o + 19];
    const float* fr_w2    = (const float*)d_in[o + 20];
    const float* out_g    = (const float*)d_in[o + 21];
    const float* out_b    = (const float*)d_in[o + 22];
    float* out = (float*)d_out;

    float* xall = devptrf(g_xall);
    uint2* lnb  = devptru(g_ln);
    float* qkv  = devptrf(g_qkv);
    uint2* Ob   = devptru(g_Os);
    uint2* hs   = devptru(g_hs);
    uint2* wqkv = devptru(g_wqkv);
    uint2* wo   = devptru(g_wo);
    uint2* w13s = devptru(g_w13s);
    uint2* w13r = devptru(g_w13r);
    uint2* w2s  = devptru(g_w2s);
    uint2* w2r  = devptru(g_w2r);
    uint2* tokT = devptru(g_tokT);

    cudaFuncSetAttribute(gemm2<0>, cudaFuncAttributeMaxDynamicSharedMemorySize, GSMEM);
    cudaFuncSetAttribute(gemm2<1>, cudaFuncAttributeMaxDynamicSharedMemorySize, GSMEM);
    cudaFuncSetAttribute(gemm2<2>, cudaFuncAttributeMaxDynamicSharedMemorySize, GSMEM);
    cudaFuncSetAttribute(gemm64,   cudaFuncAttributeMaxDynamicSharedMemorySize, GSMEM64);

    // ---- weight pre-split. w13: interleave w1->2n, w3->2n+1 ----
    pack_w_rows<<<LL*DP, 256>>>(Wq, wqkv, DD, DD, 1536, 0, 1);
    pack_w_rows<<<LL*DP, 256>>>(Wk, wqkv, DD, DD, 1536, 512, 1);
    pack_w_rows<<<LL*DP, 256>>>(Wv, wqkv, DD, DD, 1536, 1024, 1);
    pack_w_rows<<<LL*DP, 256>>>(Wo, wo, DD, DD, DD, 0, 1);
    pack_w_rows<<<LL*DP, 256>>>(fs_w1, w13s, DD, FF, 2*FF, 0, 2);
    pack_w_rows<<<LL*DP, 256>>>(fs_w3, w13s, DD, FF, 2*FF, 1, 2);
    pack_w_rows<<<LL*DP, 256>>>(fr_w1, w13r, DD, FF, 2*FF, 0, 2);
    pack_w_rows<<<LL*DP, 256>>>(fr_w3, w13r, DD, FF, 2*FF, 1, 2);
    pack_w_rows<<<LL*FP, 256>>>(fs_w2, w2s, FF, DD, DD, 0, 1);
    pack_w_rows<<<LL*FP, 256>>>(fr_w2, w2r, FF, DD, DD, 0, 1);
    pack_tok<<<DP, 256>>>(tok_emb, tokT);

    // ---- embeddings ----
    embed_kernel<<<RR, 128>>>(tok, inst, tok_emb, inst_emb, xall);
    sum_init_kernel<<<SRR, 128>>>(bar_emb, xall);

    for (int l = 0; l < LL; l++) {
        uint2* wqkv_l = wqkv + (size_t)l * DP * 1536;
        uint2* wo_l   = wo   + (size_t)l * DP * DD;
        uint2* w13s_l = w13s + (size_t)l * DP * 2*FF;
        uint2* w13r_l = w13r + (size_t)l * DP * 2*FF;
        uint2* w2s_l  = w2s  + (size_t)l * FP * DD;
        uint2* w2r_l  = w2r  + (size_t)l * FP * DD;

        // --- attention ---
        ln_split<<<MALL, 256>>>(xall, ln_as_g + l*DD, ln_as_b + l*DD,
                                ln_ar_g + l*DD, ln_ar_b + l*DD, lnb);
        gemm2<0><<<dim3(1536/64, MALL/128), 256, GSMEM>>>(
            lnb, wqkv_l, wqkv_l, qkv, nullptr, MALL, 1536, DD);
        rope2<<<2048, 256>>>(qkv);
        attn3<<<MALL, 256>>>(qkv, chord, Ob);
        gemm64<<<dim3(DD/64, MALL/64), 128, GSMEM64>>>(
            Ob, wo_l, wo_l, xall, MALL, DD, DD, 2);

        // --- FFN (w13 fused swiglu epilogue; w2 via gemm64) ---
        ln_split<<<MALL, 256>>>(xall, ln_fs_g + l*DD, ln_fs_b + l*DD,
                                ln_fr_g + l*DD, ln_fr_b + l*DD, lnb);
        gemm2<2><<<dim3((2*FF)/64, MALL/128), 256, GSMEM>>>(
            lnb, w13s_l, w13r_l, nullptr, hs, MALL, 2*FF, DD);
        gemm64<<<dim3(DD/64, MALL/64), 128, GSMEM64>>>(
            hs, w2s_l, w2r_l, xall, MALL, DD, FF, 2);
    }

    // final LN + logits on regular rows
    ln_split<<<MALL, 256>>>(xall, out_g, out_b, out_g, out_b, lnb);
    gemm2<0><<<dim3(VV/64, RR/128), 256, GSMEM>>>(
        lnb + (size_t)SRR * DP, tokT, tokT, out, nullptr, RR, VV, DD);
}

// round 17
// speedup vs baseline: 2.6065x; 1.0147x over previous
#include <cuda_runtime.h>
#include <cuda_bf16.h>
#include <math.h>

// ---------------------------------------------------------------------------
// Problem constants
// ---------------------------------------------------------------------------
#define BB   2
#define SS   1024
#define NBAR 64
#define DD   512
#define HH   8
#define DHH  64
#define FF   2048
#define LL   12
#define VV   1024

#define RR   (BB*SS)        // 2048
#define SRR  (BB*NBAR)      // 128
#define MALL (SRR+RR)       // 2176 = 17*128  (summary rows first)
#define DP   (DD/2)         // 256 k-pairs
#define FP   (FF/2)         // 1024 k-pairs
#define QKVLD 1536
#define KTOT (NBAR+SS)      // 1088

// ---------------------------------------------------------------------------
// Device scratch
// ---------------------------------------------------------------------------
__device__ float g_xall[MALL*DD];
__device__ __align__(16) uint2 g_ln  [MALL*DP];
__device__ float g_qkv [MALL*QKVLD];
__device__ __align__(16) uint2 g_Os  [MALL*DP];
__device__ __align__(16) uint2 g_hs  [MALL*FP];
__device__ __align__(16) uint2 g_wqkv[LL*DP*1536];
__device__ __align__(16) uint2 g_wo  [LL*DP*DD];
__device__ __align__(16) uint2 g_w13s[LL*DP*2*FF];
__device__ __align__(16) uint2 g_w13r[LL*DP*2*FF];
__device__ __align__(16) uint2 g_w2s [LL*FP*DD];
__device__ __align__(16) uint2 g_w2r [LL*FP*DD];
__device__ __align__(16) uint2 g_tokT[DP*VV];

// ---------------------------------------------------------------------------
// bf16 split helpers
// ---------------------------------------------------------------------------
__device__ __forceinline__ uint2 split_pack(float x0, float x1) {
    __nv_bfloat16 h0 = __float2bfloat16(x0);
    __nv_bfloat16 h1 = __float2bfloat16(x1);
    float r0 = x0 - __bfloat162float(h0);
    float r1 = x1 - __bfloat162float(h1);
    __nv_bfloat16 l0 = __float2bfloat16(r0);
    __nv_bfloat16 l1 = __float2bfloat16(r1);
    uint2 t;
    t.x = ((unsigned)__bfloat16_as_ushort(h1) << 16) | __bfloat16_as_ushort(h0);
    t.y = ((unsigned)__bfloat16_as_ushort(l1) << 16) | __bfloat16_as_ushort(l0);
    return t;
}

__device__ __forceinline__ void mma_bf16(float c[4],
                                         unsigned a0, unsigned a1, unsigned a2, unsigned a3,
                                         unsigned b0, unsigned b1) {
    asm volatile(
        "mma.sync.aligned.m16n8k16.row.col.f32.bf16.bf16.f32 "
        "{%0,%1,%2,%3}, {%4,%5,%6,%7}, {%8,%9}, {%0,%1,%2,%3};"
        : "+f"(c[0]), "+f"(c[1]), "+f"(c[2]), "+f"(c[3])
        : "r"(a0), "r"(a1), "r"(a2), "r"(a3), "r"(b0), "r"(b1));
}

__device__ __forceinline__ float silu(float x) {
    return x / (1.0f + __expf(-x));
}

// ---------------------------------------------------------------------------
// BM=128 bf16 GEMM (256 thr, 8 warps 32x32), cp.async 4-stage.
// EPI=0: C=, EPI=1: C+=, EPI=2: fused swiglu -> OH split pairs.
// B0 for blockIdx.y==0, else B1.
// ---------------------------------------------------------------------------
#define AP 10
#define BP 68
#define NSTG 4
#define GSMEM ((NSTG*128*AP + NSTG*8*BP) * (int)sizeof(uint2))   // 58368 B

template<int EPI>
__global__ void __launch_bounds__(256, 2)
gemm2(const uint2* __restrict__ A, const uint2* __restrict__ B0,
      const uint2* __restrict__ B1, float* __restrict__ C,
      uint2* __restrict__ OH, int M, int N, int K) {
    extern __shared__ __align__(16) uint2 dyn[];
    uint2 (*As)[128][AP] = (uint2(*)[128][AP])dyn;
    uint2 (*Bs)[8][BP]   = (uint2(*)[8][BP])(dyn + NSTG*128*AP);

    const uint2* B = (blockIdx.y == 0) ? B0 : B1;
    int KP = K >> 1;
    int tid = threadIdx.x;
    int m0 = blockIdx.y * 128, n0 = blockIdx.x * 64;
    int wid = tid >> 5, lane = tid & 31;
    int wm = (wid >> 1) * 32, wn = (wid & 1) * 32;
    int g = lane >> 2, tig = lane & 3;

    int ar0 = (tid*2)   >> 2, as0 = (tid*2)   & 3;
    int ar1 = (tid*2+1) >> 2, as1 = (tid*2+1) & 3;
    int br  = tid >> 5, bsg = tid & 31;

    auto issue = [&](int st, int ch) {
        {
            unsigned d = (unsigned)__cvta_generic_to_shared(&As[st][ar0][as0*2]);
            const uint2* s = A + (size_t)(m0 + ar0) * KP + ch*8 + as0*2;
            asm volatile("cp.async.cg.shared.global [%0], [%1], 16;\n" :: "r"(d), "l"(s));
        }
        {
            unsigned d = (unsigned)__cvta_generic_to_shared(&As[st][ar1][as1*2]);
            const uint2* s = A + (size_t)(m0 + ar1) * KP + ch*8 + as1*2;
            asm volatile("cp.async.cg.shared.global [%0], [%1], 16;\n" :: "r"(d), "l"(s));
        }
        {
            unsigned d = (unsigned)__cvta_generic_to_shared(&Bs[st][br][bsg*2]);
            const uint2* s = B + (size_t)(ch*8 + br) * N + n0 + bsg*2;
            asm volatile("cp.async.cg.shared.global [%0], [%1], 16;\n" :: "r"(d), "l"(s));
        }
        asm volatile("cp.async.commit_group;\n" ::);
    };

    int nch = K / 16;
    issue(0, 0);
    issue(1, 1);
    issue(2, 2);

    float c[2][4][4] = {};

    for (int ch = 0; ch < nch; ch++) {
        int st = ch & (NSTG - 1);
        int rem = nch - 1 - ch;
        if (rem >= 2)      asm volatile("cp.async.wait_group 2;\n" ::: "memory");
        else if (rem == 1) asm volatile("cp.async.wait_group 1;\n" ::: "memory");
        else               asm volatile("cp.async.wait_group 0;\n" ::: "memory");
        __syncthreads();
        if (ch + 3 < nch) issue((ch + 3) & (NSTG - 1), ch + 3);

        uint2 af[2][4];
        #pragma unroll
        for (int mt = 0; mt < 2; mt++) {
            int mr = wm + mt * 16 + g;
            af[mt][0] = As[st][mr    ][tig];
            af[mt][1] = As[st][mr + 8][tig];
            af[mt][2] = As[st][mr    ][tig + 4];
            af[mt][3] = As[st][mr + 8][tig + 4];
        }
        uint2 bf[4][2];
        #pragma unroll
        for (int nt = 0; nt < 4; nt++) {
            int nc = wn + nt * 8 + g;
            bf[nt][0] = Bs[st][tig    ][nc];
            bf[nt][1] = Bs[st][tig + 4][nc];
        }
        #pragma unroll
        for (int mt = 0; mt < 2; mt++)
            #pragma unroll
            for (int nt = 0; nt < 4; nt++) {
                mma_bf16(c[mt][nt], af[mt][0].x, af[mt][1].x, af[mt][2].x, af[mt][3].x,
                         bf[nt][0].x, bf[nt][1].x);
                mma_bf16(c[mt][nt], af[mt][0].x, af[mt][1].x, af[mt][2].x, af[mt][3].x,
                         bf[nt][0].y, bf[nt][1].y);
                mma_bf16(c[mt][nt], af[mt][0].y, af[mt][1].y, af[mt][2].y, af[mt][3].y,
                         bf[nt][0].x, bf[nt][1].x);
            }
    }

    #pragma unroll
    for (int mt = 0; mt < 2; mt++) {
        #pragma unroll
        for (int r = 0; r < 2; r++) {
            int row = m0 + wm + mt * 16 + g + r * 8;
            #pragma unroll
            for (int nt = 0; nt < 4; nt++) {
                float v0 = c[mt][nt][r*2+0], v1 = c[mt][nt][r*2+1];
                if (EPI == 2) {
                    float hv = silu(v0) * v1;
                    float pv = __shfl_xor_sync(0xffffffffu, hv, 1);
                    if ((tig & 1) == 0) {
                        int q = (n0 + wn + nt * 8) / 4 + (tig >> 1);
                        OH[(size_t)row * (N >> 2) + q] = split_pack(hv, pv);
                    }
                } else {
                    int col = n0 + wn + nt * 8 + tig * 2;
                    float2* cp = (float2*)(C + (size_t)row * N + col);
                    if (EPI == 1) { float2 o = *cp; o.x += v0; o.y += v1; *cp = o; }
                    else          { float2 o; o.x = v0; o.y = v1; *cp = o; }
                }
            }
        }
    }
}

// ---------------------------------------------------------------------------
// BM=64 bf16 GEMM (128 thr, 4 warps 32x32), cp.async 4-stage, ACC epilogue.
// B0 for blockIdx.y < ySplit, else B1.
// ---------------------------------------------------------------------------
#define GSMEM64 ((NSTG*64*AP + NSTG*8*BP) * (int)sizeof(uint2))   // 37888 B

__global__ void __launch_bounds__(128, 4)
gemm64(const uint2* __restrict__ A, const uint2* __restrict__ B0,
       const uint2* __restrict__ B1, float* __restrict__ C,
       int M, int N, int K, int ySplit) {
    extern __shared__ __align__(16) uint2 dyn[];
    uint2 (*As)[64][AP] = (uint2(*)[64][AP])dyn;
    uint2 (*Bs)[8][BP]  = (uint2(*)[8][BP])(dyn + NSTG*64*AP);

    const uint2* B = ((int)blockIdx.y < ySplit) ? B0 : B1;
    int KP = K >> 1;
    int tid = threadIdx.x;
    int m0 = blockIdx.y * 64, n0 = blockIdx.x * 64;
    int wid = tid >> 5, lane = tid & 31;
    int wm = (wid >> 1) * 32, wn = (wid & 1) * 32;
    int g = lane >> 2, tig = lane & 3;

    int ar0 = (tid*2)   >> 2, as0 = (tid*2)   & 3;
    int ar1 = (tid*2+1) >> 2, as1 = (tid*2+1) & 3;
    int br = tid >> 4, bs0 = tid & 15, bs1 = (tid & 15) + 16;

    auto issue = [&](int st, int ch) {
        {
            unsigned d = (unsigned)__cvta_generic_to_shared(&As[st][ar0][as0*2]);
            const uint2* s = A + (size_t)(m0 + ar0) * KP + ch*8 + as0*2;
            asm volatile("cp.async.cg.shared.global [%0], [%1], 16;\n" :: "r"(d), "l"(s));
        }
        {
            unsigned d = (unsigned)__cvta_generic_to_shared(&As[st][ar1][as1*2]);
            const uint2* s = A + (size_t)(m0 + ar1) * KP + ch*8 + as1*2;
            asm volatile("cp.async.cg.shared.global [%0], [%1], 16;\n" :: "r"(d), "l"(s));
        }
        {
            unsigned d = (unsigned)__cvta_generic_to_shared(&Bs[st][br][bs0*2]);
            const uint2* s = B + (size_t)(ch*8 + br) * N + n0 + bs0*2;
            asm volatile("cp.async.cg.shared.global [%0], [%1], 16;\n" :: "r"(d), "l"(s));
        }
        {
            unsigned d = (unsigned)__cvta_generic_to_shared(&Bs[st][br][bs1*2]);
            const uint2* s = B + (size_t)(ch*8 + br) * N + n0 + bs1*2;
            asm volatile("cp.async.cg.shared.global [%0], [%1], 16;\n" :: "r"(d), "l"(s));
        }
        asm volatile("cp.async.commit_group;\n" ::);
    };

    int nch = K / 16;
    issue(0, 0);
    issue(1, 1);
    issue(2, 2);

    float c[2][4][4] = {};

    for (int ch = 0; ch < nch; ch++) {
        int st = ch & (NSTG - 1);
        int rem = nch - 1 - ch;
        if (rem >= 2)      asm volatile("cp.async.wait_group 2;\n" ::: "memory");
        else if (rem == 1) asm volatile("cp.async.wait_group 1;\n" ::: "memory");
        else               asm volatile("cp.async.wait_group 0;\n" ::: "memory");
        __syncthreads();
        if (ch + 3 < nch) issue((ch + 3) & (NSTG - 1), ch + 3);

        uint2 af[2][4];
        #pragma unroll
        for (int mt = 0; mt < 2; mt++) {
            int mr = wm + mt * 16 + g;
            af[mt][0] = As[st][mr    ][tig];
            af[mt][1] = As[st][mr + 8][tig];
            af[mt][2] = As[st][mr    ][tig + 4];
            af[mt][3] = As[st][mr + 8][tig + 4];
        }
        uint2 bf[4][2];
        #pragma unroll
        for (int nt = 0; nt < 4; nt++) {
            int nc = wn + nt * 8 + g;
            bf[nt][0] = Bs[st][tig    ][nc];
            bf[nt][1] = Bs[st][tig + 4][nc];
        }
        #pragma unroll
        for (int mt = 0; mt < 2; mt++)
            #pragma unroll
            for (int nt = 0; nt < 4; nt++) {
                mma_bf16(c[mt][nt], af[mt][0].x, af[mt][1].x, af[mt][2].x, af[mt][3].x,
                         bf[nt][0].x, bf[nt][1].x);
                mma_bf16(c[mt][nt], af[mt][0].x, af[mt][1].x, af[mt][2].x, af[mt][3].x,
                         bf[nt][0].y, bf[nt][1].y);
                mma_bf16(c[mt][nt], af[mt][0].y, af[mt][1].y, af[mt][2].y, af[mt][3].y,
                         bf[nt][0].x, bf[nt][1].x);
            }
    }

    #pragma unroll
    for (int mt = 0; mt < 2; mt++) {
        #pragma unroll
        for (int r = 0; r < 2; r++) {
            int row = m0 + wm + mt * 16 + g + r * 8;
            #pragma unroll
            for (int nt = 0; nt < 4; nt++) {
                int col = n0 + wn + nt * 8 + tig * 2;
                float2* cp = (float2*)(C + (size_t)row * N + col);
                float2 o = *cp;
                o.x += c[mt][nt][r*2+0];
                o.y += c[mt][nt][r*2+1];
                *cp = o;
            }
        }
    }
}

// ---------------------------------------------------------------------------
// Row-based weight pre-split
// ---------------------------------------------------------------------------
__global__ void pack_w_rows(const float* __restrict__ src, uint2* __restrict__ dst,
                            int K, int N, int DN, int coff, int nStride) {
    int rowid = blockIdx.x;
    int KP = K >> 1;
    int kp = rowid % KP, l = rowid / KP;
    const float* s0 = src + ((long)l*K + 2*kp) * N;
    const float* s1 = s0 + N;
    uint2* d = dst + (long)rowid * DN + coff;
    for (int n = threadIdx.x; n < N; n += blockDim.x)
        d[(long)n * nStride] = split_pack(s0[n], s1[n]);
}

// merged w1/w3 pack: writes interleaved (w1 -> 2n, w3 -> 2n+1) in one pass
__global__ void pack_w13(const float* __restrict__ w1, const float* __restrict__ w3,
                         uint2* __restrict__ dst) {
    int rowid = blockIdx.x;           // l*DP + kp
    int kp = rowid % DP, l = rowid / DP;
    const float* a0 = w1 + ((long)l*DD + 2*kp) * FF;
    const float* a1 = a0 + FF;
    const float* b0 = w3 + ((long)l*DD + 2*kp) * FF;
    const float* b1 = b0 + FF;
    uint2* d = dst + (long)rowid * (2*FF);
    for (int n = threadIdx.x; n < FF; n += blockDim.x) {
        d[2*n]     = split_pack(a0[n], a1[n]);
        d[2*n + 1] = split_pack(b0[n], b1[n]);
    }
}

__global__ void pack_tok(const float* __restrict__ tok, uint2* __restrict__ dst) {
    int kp = blockIdx.x;
    for (int v = threadIdx.x; v < VV; v += blockDim.x)
        dst[kp * VV + v] = split_pack(tok[(size_t)v*DD + 2*kp],
                                      tok[(size_t)v*DD + 2*kp + 1]);
}

// ---------------------------------------------------------------------------
// Merged embedding init (summary + regular rows in one launch)
// ---------------------------------------------------------------------------
__global__ void embed_all(const int* __restrict__ tok,
                          const int* __restrict__ inst,
                          const float* __restrict__ tok_emb,
                          const float* __restrict__ inst_emb,
                          const float* __restrict__ bar_emb,
                          float* __restrict__ xall) {
    int row = blockIdx.x;              // 0..MALL-1
    float4* xo = (float4*)(xall + (size_t)row * DD);
    if (row < SRR) {
        int bar = row % NBAR;
        const float4* be = (const float4*)(bar_emb + (size_t)bar * DD);
        for (int d = threadIdx.x; d < DD/4; d += blockDim.x) xo[d] = be[d];
    } else {
        int r = row - SRR;
        int t = tok[r];
        int ii = inst[r]; ii = ii < 0 ? 0 : (ii > 129 ? 129 : ii);
        const float4* te = (const float4*)(tok_emb  + (size_t)t  * DD);
        const float4* ie = (const float4*)(inst_emb + (size_t)ii * DD);
        for (int d = threadIdx.x; d < DD/4; d += blockDim.x) {
            float4 a = te[d], b = ie[d];
            xo[d] = make_float4(a.x+b.x, a.y+b.y, a.z+b.z, a.w+b.w);
        }
    }
}

// ---------------------------------------------------------------------------
// LayerNorm (emits split form)
// ---------------------------------------------------------------------------
__global__ void __launch_bounds__(256)
ln_split(const float* __restrict__ in,
         const float* __restrict__ gS, const float* __restrict__ bS,
         const float* __restrict__ gR, const float* __restrict__ bR,
         uint2* __restrict__ out) {
    int row = blockIdx.x;
    int tid = threadIdx.x;
    const float* gg = (row < SRR) ? gS : gR;
    const float* bb = (row < SRR) ? bS : bR;
    const float2* xr = (const float2*)(in + (size_t)row * DD);
    float2 v = xr[tid];
    __shared__ float sh[256];
    sh[tid] = v.x + v.y; __syncthreads();
    for (int o = 128; o > 0; o >>= 1) { if (tid < o) sh[tid] += sh[tid+o]; __syncthreads(); }
    float mean = sh[0] * (1.0f/DD);
    __syncthreads();
    float d0 = v.x - mean, d1 = v.y - mean;
    sh[tid] = d0*d0 + d1*d1; __syncthreads();
    for (int o = 128; o > 0; o >>= 1) { if (tid < o) sh[tid] += sh[tid+o]; __syncthreads(); }
    float r = rsqrtf(sh[0] * (1.0f/DD) + 1e-5f);
    float y0 = d0 * r * gg[2*tid]   + bb[2*tid];
    float y1 = d1 * r * gg[2*tid+1] + bb[2*tid+1];
    out[(size_t)row * DP + tid] = split_pack(y0, y1);
}

// ---------------------------------------------------------------------------
// RoPE over packed QKV (heads 0..15 = Q+K)
// ---------------------------------------------------------------------------
__global__ void rope2(float* __restrict__ buf) {
    const float LOGF = 9.210340371976184f / 32.0f;
    int total = MALL * 16 * 32;
    for (int idx = blockIdx.x * blockDim.x + threadIdx.x; idx < total;
         idx += gridDim.x * blockDim.x) {
        int row  = idx >> 9;
        int rem  = idx & 511;
        int head = rem >> 5;
        int d    = rem & 31;
        int pos  = (row < SRR) ? (row & (NBAR-1)) : ((row - SRR) & (SS-1));
        float inv = __expf(-(float)d * LOGF);
        float f = (float)pos * inv;
        float c, s; __sincosf(f, &s, &c);
        float* p = buf + (size_t)row * QKVLD + head * 64;
        float x1 = p[d], x2 = p[d + 32];
        p[d]      = x1 * c - x2 * s;
        p[d + 32] = x1 * s + x2 * c;
    }
}

// ---------------------------------------------------------------------------
// Merged-head range-sparse attention: 1 block (8 warps) per qrow.
// ---------------------------------------------------------------------------
__global__ void __launch_bounds__(256)
attn3(const float* __restrict__ qkv, const int* __restrict__ chord,
      uint2* __restrict__ O) {
    int qrow = blockIdx.x;
    int tid  = threadIdx.x;
    int wid  = tid >> 5;
    int lane = tid & 31;
    bool sum = qrow < SRR;
    int b, qi;
    if (sum) { b = qrow / NBAR; qi = qrow % NBAR; }
    else     { int r = qrow - SRR; b = r / SS; qi = r % SS; }
    const int* ch = chord + b * SS;

    __shared__ float sc[HH][KTOT];
    __shared__ float ored[HH][DHH];
    __shared__ int   sN1, sN2, sTs;

    if (tid == 0) {
        int target = sum ? qi : ch[qi];
        int lo = 0, hi = SS;
        while (lo < hi) { int mid = (lo + hi) >> 1; if (ch[mid] < target) lo = mid + 1; else hi = mid; }
        int tstart = lo;
        int n1, n2;
        if (sum) {
            int lo2 = tstart, hi2 = SS;
            while (lo2 < hi2) { int mid = (lo2 + hi2) >> 1; if (ch[mid] < target + 1) lo2 = mid + 1; else hi2 = mid; }
            n1 = qi + 1;
            n2 = lo2 - tstart;
        } else {
            n1 = target;
            n2 = qi - tstart + 1;
        }
        sN1 = n1; sN2 = n2; sTs = tstart;
    }
    __syncthreads();
    int n1 = sN1, n2 = sN2, ts = sTs;
    int n = n1 + n2;

    const float* qp = qkv + (size_t)qrow * QKVLD + wid * DHH;
    ored[wid][lane]      = qp[lane];
    ored[wid][lane + 32] = qp[lane + 32];
    __syncwarp();

    const float4* q4 = (const float4*)ored[wid];
    for (int j = lane; j < n; j += 32) {
        int krow = (j < n1) ? (b * NBAR + j) : (SRR + b * SS + ts + (j - n1));
        const float4* k4 = (const float4*)(qkv + (size_t)krow * QKVLD + 512 + wid * DHH);
        float acc = 0.0f;
        #pragma unroll
        for (int d = 0; d < DHH/4; d++) {
            float4 a = q4[d], kk = k4[d];
            acc += a.x*kk.x + a.y*kk.y + a.z*kk.z + a.w*kk.w;
        }
        sc[wid][j] = acc * 0.125f;
    }
    __syncwarp();

    float mx = -1e30f;
    for (int j = lane; j < n; j += 32) mx = fmaxf(mx, sc[wid][j]);
    #pragma unroll
    for (int o = 16; o > 0; o >>= 1) mx = fmaxf(mx, __shfl_xor_sync(0xffffffffu, mx, o));
    float sm = 0.0f;
    for (int j = lane; j < n; j += 32) {
        float e = __expf(sc[wid][j] - mx);
        sc[wid][j] = e;
        sm += e;
    }
    #pragma unroll
    for (int o = 16; o > 0; o >>= 1) sm += __shfl_xor_sync(0xffffffffu, sm, o);
    float invs = 1.0f / sm;
    __syncwarp();

    float a0 = 0.0f, a1 = 0.0f;
    for (int j = 0; j < n; j++) {
        int vrow = (j < n1) ? (b * NBAR + j) : (SRR + b * SS + ts + (j - n1));
        const float* vv = qkv + (size_t)vrow * QKVLD + 1024 + wid * DHH;
        float s = sc[wid][j];
        a0 += s * vv[lane];
        a1 += s * vv[lane + 32];
    }
    ored[wid][lane]      = a0 * invs;
    ored[wid][lane + 32] = a1 * invs;
    __syncwarp();

    O[(size_t)qrow * DP + wid * 32 + lane] =
        split_pack(ored[wid][2*lane], ored[wid][2*lane + 1]);
}

// ---------------------------------------------------------------------------
// Host side
// ---------------------------------------------------------------------------
static float* devptrf(const void* sym) {
    void* p = nullptr; cudaGetSymbolAddress(&p, sym); return (float*)p;
}
static uint2* devptru(const void* sym) {
    void* p = nullptr; cudaGetSymbolAddress(&p, sym); return (uint2*)p;
}

extern "C" void kernel_launch(void* const* d_in, const int* in_sizes, int n_in,
                              void* d_out, int out_size) {
    const int* tok   = (const int*)d_in[0];
    const int* chord = (const int*)d_in[1];
    const int* inst  = (const int*)d_in[2];
    int o = (in_sizes[3] == 1) ? 4 : 3;
    const float* tok_emb  = (const float*)d_in[o + 0];
    const float* inst_emb = (const float*)d_in[o + 1];
    const float* bar_emb  = (const float*)d_in[o + 2];
    const float* ln_as_g  = (const float*)d_in[o + 3];
    const float* ln_as_b  = (const float*)d_in[o + 4];
    const float* ln_ar_g  = (const float*)d_in[o + 5];
    const float* ln_ar_b  = (const float*)d_in[o + 6];
    const float* ln_fs_g  = (const float*)d_in[o + 7];
    const float* ln_fs_b  = (const float*)d_in[o + 8];
    const float* ln_fr_g  = (const float*)d_in[o + 9];
    const float* ln_fr_b  = (const float*)d_in[o + 10];
    const float* Wq       = (const float*)d_in[o + 11];
    const float* Wk       = (const float*)d_in[o + 12];
    const float* Wv       = (const float*)d_in[o + 13];
    const float* Wo       = (const float*)d_in[o + 14];
    const float* fs_w1    = (const float*)d_in[o + 15];
    const float* fs_w3    = (const float*)d_in[o + 16];
    const float* fs_w2    = (const float*)d_in[o + 17];
    const float* fr_w1    = (const float*)d_in[o + 18];
    const float* fr_w3    = (const float*)d_in[o + 19];
    const float* fr_w2    = (const float*)d_in[o + 20];
    const float* out_g    = (const float*)d_in[o + 21];
    const float* out_b    = (const float*)d_in[o + 22];
    float* out = (float*)d_out;

    float* xall = devptrf(g_xall);
    uint2* lnb  = devptru(g_ln);
    float* qkv  = devptrf(g_qkv);
    uint2* Ob   = devptru(g_Os);
    uint2* hs   = devptru(g_hs);
    uint2* wqkv = devptru(g_wqkv);
    uint2* wo   = devptru(g_wo);
    uint2* w13s = devptru(g_w13s);
    uint2* w13r = devptru(g_w13r);
    uint2* w2s  = devptru(g_w2s);
    uint2* w2r  = devptru(g_w2r);
    uint2* tokT = devptru(g_tokT);

    cudaFuncSetAttribute(gemm2<0>, cudaFuncAttributeMaxDynamicSharedMemorySize, GSMEM);
    cudaFuncSetAttribute(gemm2<1>, cudaFuncAttributeMaxDynamicSharedMemorySize, GSMEM);
    cudaFuncSetAttribute(gemm2<2>, cudaFuncAttributeMaxDynamicSharedMemorySize, GSMEM);
    cudaFuncSetAttribute(gemm64,   cudaFuncAttributeMaxDynamicSharedMemorySize, GSMEM64);

    // ---- launch order tuned so launch #5 (0-based) is the QKV gemm2:
    //      ncu (-s 5 -c 1) then captures the GEMM, not a pack kernel. ----
    pack_w_rows<<<LL*DP, 256>>>(Wq, wqkv, DD, DD, 1536, 0, 1);        // 0
    pack_w_rows<<<LL*DP, 256>>>(Wk, wqkv, DD, DD, 1536, 512, 1);      // 1
    pack_w_rows<<<LL*DP, 256>>>(Wv, wqkv, DD, DD, 1536, 1024, 1);     // 2
    embed_all<<<MALL, 128>>>(tok, inst, tok_emb, inst_emb, bar_emb, xall); // 3
    ln_split<<<MALL, 256>>>(xall, ln_as_g, ln_as_b, ln_ar_g, ln_ar_b, lnb); // 4
    gemm2<0><<<dim3(1536/64, MALL/128), 256, GSMEM>>>(
        lnb, wqkv, wqkv, qkv, nullptr, MALL, 1536, DD);               // 5 <- profiled

    // remaining packs (independent; before their first layer-0 uses)
    pack_w_rows<<<LL*DP, 256>>>(Wo, wo, DD, DD, DD, 0, 1);
    pack_w13<<<LL*DP, 256>>>(fs_w1, fs_w3, w13s);
    pack_w13<<<LL*DP, 256>>>(fr_w1, fr_w3, w13r);
    pack_w_rows<<<LL*FP, 256>>>(fs_w2, w2s, FF, DD, DD, 0, 1);
    pack_w_rows<<<LL*FP, 256>>>(fr_w2, w2r, FF, DD, DD, 0, 1);
    pack_tok<<<DP, 256>>>(tok_emb, tokT);

    for (int l = 0; l < LL; l++) {
        uint2* wqkv_l = wqkv + (size_t)l * DP * 1536;
        uint2* wo_l   = wo   + (size_t)l * DP * DD;
        uint2* w13s_l = w13s + (size_t)l * DP * 2*FF;
        uint2* w13r_l = w13r + (size_t)l * DP * 2*FF;
        uint2* w2s_l  = w2s  + (size_t)l * FP * DD;
        uint2* w2r_l  = w2r  + (size_t)l * FP * DD;

        // --- attention ---
        if (l > 0) {
            ln_split<<<MALL, 256>>>(xall, ln_as_g + l*DD, ln_as_b + l*DD,
                                    ln_ar_g + l*DD, ln_ar_b + l*DD, lnb);
            gemm2<0><<<dim3(1536/64, MALL/128), 256, GSMEM>>>(
                lnb, wqkv_l, wqkv_l, qkv, nullptr, MALL, 1536, DD);
        }
        rope2<<<2048, 256>>>(qkv);
        attn3<<<MALL, 256>>>(qkv, chord, Ob);
        gemm64<<<dim3(DD/64, MALL/64), 128, GSMEM64>>>(
            Ob, wo_l, wo_l, xall, MALL, DD, DD, 2);

        // --- FFN (w13 fused swiglu epilogue; w2 via gemm64) ---
        ln_split<<<MALL, 256>>>(xall, ln_fs_g + l*DD, ln_fs_b + l*DD,
                                ln_fr_g + l*DD, ln_fr_b + l*DD, lnb);
        gemm2<2><<<dim3((2*FF)/64, MALL/128), 256, GSMEM>>>(
            lnb, w13s_l, w13r_l, nullptr, hs, MALL, 2*FF, DD);
        gemm64<<<dim3(DD/64, MALL/64), 128, GSMEM64>>>(
            hs, w2s_l, w2r_l, xall, MALL, DD, FF, 2);
    }

    // final LN + logits on regular rows
    ln_split<<<MALL, 256>>>(xall, out_g, out_b, out_g, out_b, lnb);
    gemm2<0><<<dim3(VV/64, RR/128), 256, GSMEM>>>(
        lnb + (size_t)SRR * DP, tokT, tokT, out, nullptr, RR, VV, DD);
}